// round 14
// baseline (speedup 1.0000x reference)
#include <cuda_runtime.h>
#include <cuda_fp16.h>

#define N_NODES   50000
#define N_EDGES   2400000
#define NUM_GRAPHS 2048
#define NSLOT     (3 * N_NODES)          // 150000 hop-slots
#define NCHUNK    ((NSLOT + 1023) / 1024) // 147
#define HID       128
#define GEMM_BLKS ((N_NODES + 127) / 128)   // 391
#define ASTR 20    // smem stride for proj streamed tiles (tf32 path)
#define XSTR 132   // smem stride (u32) for resident fp32 state
#define HSTR 68    // smem stride (u32) for resident fp16 buffers
#define CSTR 20    // smem stride (u32) for streamed fp16 chunks
#define ABUF (128 * CSTR + 256 * CSTR)   // one phase-A buffer (u32)
#define NWA  (3 * 512 * 256)             // phase-A weight elements
#define NWM  (3 * 2 * 2 * 128 * 128)     // MLP weight elements

// ---------------- scratch (static device memory; no allocs) ----------------
__device__ __align__(16) float  g_x[N_NODES * HID];
__device__ __align__(16) __half g_xh[N_NODES * HID];             // fp16 mirror of x
__device__ __align__(16) __half g_hops16[(size_t)N_NODES * 384]; // fp16 hop sums
__device__ __align__(16) float  g_gskip[N_NODES * HID];
// interleaved fp16 weights: [kc][n][8] tiles (kc = k/8) -> coalesced uint4 loads
__device__ __align__(16) __half g_w16A[3 * 64 * 256 * 8];        // phase A: [l][kc][n][8]
__device__ __align__(16) __half g_w16M[3 * 2 * 2 * 16 * 128 * 8];// MLP: [lm][ph][kc][n][8]
__device__ int g_cnt[NSLOT];             // zero-init; reset each launch by scan_within
__device__ int g_csum[NCHUNK];
__device__ int g_coff[NCHUNK];
__device__ int g_rowptr[NSLOT + 1];
__device__ int g_cursor[NSLOT];
__device__ int g_esrc[N_EDGES];

__device__ __forceinline__ float silu(float v) { return v / (1.f + __expf(-v)); }

__device__ __forceinline__ unsigned f2tf32(float v) {
    unsigned r;
    asm("cvt.rna.tf32.f32 %0, %1;" : "=r"(r) : "f"(v));
    return r;
}
__device__ __forceinline__ unsigned pack_half2(float a, float b) {
    __half2 h = __floats2half2_rn(a, b);
    return *(unsigned*)&h;
}
__device__ __forceinline__ void ldsm4(unsigned r[4], const unsigned* p) {
    unsigned a = (unsigned)__cvta_generic_to_shared(p);
    asm volatile("ldmatrix.sync.aligned.m8n8.x4.shared.b16 {%0,%1,%2,%3}, [%4];"
                 : "=r"(r[0]), "=r"(r[1]), "=r"(r[2]), "=r"(r[3]) : "r"(a));
}

#define MMA_TF32(cc, aa, bb) \
    asm volatile("mma.sync.aligned.m16n8k8.row.col.f32.tf32.tf32.f32 " \
                 "{%0,%1,%2,%3},{%4,%5,%6,%7},{%8,%9},{%0,%1,%2,%3};" \
                 : "+f"(cc[0]), "+f"(cc[1]), "+f"(cc[2]), "+f"(cc[3]) \
                 : "r"(aa[0]), "r"(aa[1]), "r"(aa[2]), "r"(aa[3]), \
                   "r"(bb[0]), "r"(bb[1]))

#define MMA_F16(cc, aa, b0v, b1v) \
    asm volatile("mma.sync.aligned.m16n8k16.row.col.f32.f16.f16.f32 " \
                 "{%0,%1,%2,%3},{%4,%5,%6,%7},{%8,%9},{%0,%1,%2,%3};" \
                 : "+f"(cc[0]), "+f"(cc[1]), "+f"(cc[2]), "+f"(cc[3]) \
                 : "r"(aa[0]), "r"(aa[1]), "r"(aa[2]), "r"(aa[3]), \
                   "r"(b0v), "r"(b1v))

// ========= weight pre-conversion to interleaved fp16 [kc][n][8] (one launch) =
__global__ void convert_w_kernel(const float* __restrict__ in_w,
                                 const float* __restrict__ skip_w,
                                 const float* __restrict__ w1,
                                 const float* __restrict__ w2) {
    int idx = blockIdx.x * blockDim.x + threadIdx.x;
    if (idx < NWA) {
        int l = idx / (512 * 256);
        int rem = idx % (512 * 256);
        int k = rem >> 8;
        int n = rem & 255;
        const float* src = (n < 128) ? in_w : skip_w;
        float v = src[(size_t)l * 512 * 128 + (size_t)k * 128 + (n & 127)];
        size_t dst = (((size_t)l * 64 + (k >> 3)) * 256 + n) * 8 + (k & 7);
        g_w16A[dst] = __float2half(v);
    } else if (idx < NWA + NWM) {
        int j = idx - NWA;
        int panel = j >> 14;
        int rem = j & 0x3FFF;
        int k = rem >> 7;
        int n = rem & 127;
        int phase = panel & 1;
        int lm = panel >> 1;
        const float* src = phase ? w2 : w1;
        float v = src[(size_t)lm * 16384 + (size_t)k * 128 + n];
        size_t dst = (((size_t)panel * 16 + (k >> 3)) * 128 + n) * 8 + (k & 7);
        g_w16M[dst] = __float2half(v);
    }
}

// ================= CSR build =================
__global__ void count_kernel(const int* __restrict__ tgt) {
    int e = blockIdx.x * blockDim.x + threadIdx.x;
    if (e < N_EDGES) atomicAdd(&g_cnt[tgt[e]], 1);
}
__global__ void chunk_sum_kernel() {
    __shared__ int red[256];
    int b = blockIdx.x, t = threadIdx.x;
    int s = 0;
#pragma unroll
    for (int j = 0; j < 4; j++) {
        int i = b * 1024 + j * 256 + t;
        if (i < NSLOT) s += g_cnt[i];
    }
    red[t] = s; __syncthreads();
    for (int o = 128; o > 0; o >>= 1) {
        if (t < o) red[t] += red[t + o];
        __syncthreads();
    }
    if (t == 0) g_csum[b] = red[0];
}
__global__ void scan_chunks_kernel() {
    __shared__ int buf[2][256];
    int t = threadIdx.x;
    int v = (t < NCHUNK) ? g_csum[t] : 0;
    buf[0][t] = v;
    __syncthreads();
    int cur = 0;
#pragma unroll
    for (int off = 1; off < 256; off <<= 1) {
        int nv = buf[cur][t] + ((t >= off) ? buf[cur][t - off] : 0);
        buf[cur ^ 1][t] = nv;
        cur ^= 1;
        __syncthreads();
    }
    if (t < NCHUNK) g_coff[t] = buf[cur][t] - v;
    if (t == NCHUNK - 1) g_rowptr[NSLOT] = buf[cur][t];
}
__global__ void scan_within_kernel() {
    __shared__ int buf[2][1024];
    int b = blockIdx.x, t = threadIdx.x;
    int i = b * 1024 + t;
    int v = (i < NSLOT) ? g_cnt[i] : 0;
    buf[0][t] = v;
    __syncthreads();
    int cur = 0;
#pragma unroll
    for (int off = 1; off < 1024; off <<= 1) {
        int nv = buf[cur][t] + ((t >= off) ? buf[cur][t - off] : 0);
        buf[cur ^ 1][t] = nv;
        cur ^= 1;
        __syncthreads();
    }
    if (i < NSLOT) {
        int excl = buf[cur][t] - v;
        int rp = g_coff[b] + excl;
        g_rowptr[i] = rp;
        g_cursor[i] = rp;
        g_cnt[i] = 0;   // reset for next launch (graph replay)
    }
}
__global__ void fill_kernel(const int* __restrict__ tgt, const int* __restrict__ srcv) {
    int e = blockIdx.x * blockDim.x + threadIdx.x;
    if (e >= N_EDGES) return;
    int t = tgt[e];
    int pos = atomicAdd(&g_cursor[t], 1);
    g_esrc[pos] = srcv[e] % N_NODES;
}

// ================= hop gather: fp16 rows, fp32 accum, 8-way ILP ==============
__global__ __launch_bounds__(256) void gather_hops_kernel() {
    int slot = (blockIdx.x * blockDim.x + threadIdx.x) >> 5;
    int lane = threadIdx.x & 31;
    if (slot >= NSLOT) return;
    int beg = g_rowptr[slot], end = g_rowptr[slot + 1];
    float4 acc[8];
#pragma unroll
    for (int q = 0; q < 8; q++) acc[q] = make_float4(0.f, 0.f, 0.f, 0.f);
    const uint2* xh = (const uint2*)g_xh;
    int e = beg;
    for (; e + 7 < end; e += 8) {
        uint2 u[8];
#pragma unroll
        for (int q = 0; q < 8; q++) u[q] = xh[(size_t)g_esrc[e + q] * 32 + lane];
#pragma unroll
        for (int q = 0; q < 8; q++) {
            float2 f;
            f = __half22float2(*(__half2*)&u[q].x); acc[q].x += f.x; acc[q].y += f.y;
            f = __half22float2(*(__half2*)&u[q].y); acc[q].z += f.x; acc[q].w += f.y;
        }
    }
    for (; e < end; e++) {
        uint2 u0 = xh[(size_t)g_esrc[e] * 32 + lane];
        float2 f;
        f = __half22float2(*(__half2*)&u0.x); acc[0].x += f.x; acc[0].y += f.y;
        f = __half22float2(*(__half2*)&u0.y); acc[0].z += f.x; acc[0].w += f.y;
    }
#pragma unroll
    for (int q = 1; q < 8; q++) {
        acc[0].x += acc[q].x; acc[0].y += acc[q].y;
        acc[0].z += acc[q].z; acc[0].w += acc[q].w;
    }
    int node = slot % N_NODES, hop = slot / N_NODES;
    uint2 o;
    o.x = pack_half2(acc[0].x, acc[0].y);
    o.y = pack_half2(acc[0].z, acc[0].w);
    ((uint2*)g_hops16)[(size_t)node * 96 + hop * 32 + lane] = o;
}

// ================= fused embed+proj GEMM (single-pass tf32) =================
__global__ __launch_bounds__(256) void proj_kernel(
    const int* __restrict__ atom, const int* __restrict__ hyd,
    const int* __restrict__ deg,  const int* __restrict__ hyb,
    const float* __restrict__ ea, const float* __restrict__ eh,
    const float* __restrict__ ed, const float* __restrict__ ey,
    const float* __restrict__ B, const float* __restrict__ bias) {
    __shared__ unsigned Ah[128 * ASTR];
    __shared__ unsigned Bh[128 * ASTR];
    __shared__ int sidx[128][4];

    const int tid  = threadIdx.x;
    const int lane = tid & 31, wid = tid >> 5;
    const int wm = (wid >> 2) * 64;
    const int wn = (wid & 3) * 32;
    const int grp = lane >> 2, tg = lane & 3;
    const int row0 = blockIdx.x * 128;

    if (tid < 128) {
        int gr = row0 + tid;
        int g2 = (gr < N_NODES) ? gr : 0;
        sidx[tid][0] = atom[g2];
        sidx[tid][1] = hyd[g2];
        sidx[tid][2] = deg[g2];
        sidx[tid][3] = hyb[g2];
    }
    __syncthreads();
    const float* tabs[4] = {ea, eh, ed, ey};

    float c[4][4][4];
#pragma unroll
    for (int i = 0; i < 4; i++)
#pragma unroll
        for (int j = 0; j < 4; j++)
#pragma unroll
            for (int q = 0; q < 4; q++) c[i][j][q] = 0.f;

    const int ar  = tid >> 2;
    const int ac4 = (tid & 3) * 4;
    const int bn  = tid & 127;
    const int bk0 = (tid >> 7) * 8;

    for (int k0 = 0; k0 < 256; k0 += 16) {
        float4 av[2]; float bv[8];
        int kt = (k0 + ac4) >> 6, kw = (k0 + ac4) & 63;
#pragma unroll
        for (int it = 0; it < 2; it++) {
            int r = ar + it * 64;
            av[it] = *(const float4*)(tabs[kt] + (size_t)sidx[r][kt] * 64 + kw);
        }
#pragma unroll
        for (int kk = 0; kk < 8; kk++) bv[kk] = B[(size_t)(k0 + bk0 + kk) * 128 + bn];

        __syncthreads();
#pragma unroll
        for (int it = 0; it < 2; it++) {
            int r = ar + it * 64;
            float vv[4] = {av[it].x, av[it].y, av[it].z, av[it].w};
#pragma unroll
            for (int j = 0; j < 4; j++) Ah[r * ASTR + ac4 + j] = f2tf32(vv[j]);
        }
#pragma unroll
        for (int kk = 0; kk < 8; kk++) Bh[bn * ASTR + bk0 + kk] = f2tf32(bv[kk]);
        __syncthreads();
#pragma unroll
        for (int s = 0; s < 2; s++) {
            const int ks = s * 8;
            unsigned bh[4][2];
#pragma unroll
            for (int nf = 0; nf < 4; nf++) {
                int b0 = (wn + nf * 8 + grp) * ASTR + ks + tg;
                bh[nf][0] = Bh[b0]; bh[nf][1] = Bh[b0 + 4];
            }
#pragma unroll
            for (int mf = 0; mf < 4; mf++) {
                unsigned ah[4];
                int a0 = (wm + mf * 16 + grp) * ASTR + ks + tg;
                int a1 = a0 + 8 * ASTR;
                ah[0] = Ah[a0]; ah[1] = Ah[a1]; ah[2] = Ah[a0 + 4]; ah[3] = Ah[a1 + 4];
#pragma unroll
                for (int nf = 0; nf < 4; nf++) MMA_TF32(c[mf][nf], ah, bh[nf]);
            }
        }
    }

#pragma unroll
    for (int mf = 0; mf < 4; mf++) {
        int r0 = row0 + wm + mf * 16 + grp;
        int r1 = r0 + 8;
#pragma unroll
        for (int nf = 0; nf < 4; nf++) {
            int col = wn + nf * 8 + 2 * tg;
            float bia0 = bias[col], bia1 = bias[col + 1];
            if (r0 < N_NODES) {
                float v0 = silu(c[mf][nf][0] + bia0), v1 = silu(c[mf][nf][1] + bia1);
                g_x[(size_t)r0 * 128 + col]     = v0;
                g_x[(size_t)r0 * 128 + col + 1] = v1;
                *(unsigned*)&g_xh[(size_t)r0 * 128 + col] = pack_half2(v0, v1);
            }
            if (r1 < N_NODES) {
                float v2 = silu(c[mf][nf][2] + bia0), v3 = silu(c[mf][nf][3] + bia1);
                g_x[(size_t)r1 * 128 + col]     = v2;
                g_x[(size_t)r1 * 128 + col + 1] = v3;
                *(unsigned*)&g_xh[(size_t)r1 * 128 + col] = pack_half2(v2, v3);
            }
        }
    }
}

// ================= mega layer kernel (fp16 MMA via ldmatrix) =================
__device__ __forceinline__ const __half* feat16_ptr(int gr, int k) {
    return (k < 128) ? (g_xh + (size_t)gr * 128 + k)
                     : (g_hops16 + (size_t)gr * 384 + (k - 128));
}

__global__ __launch_bounds__(512, 1) void layer_kernel(
    const float* __restrict__ in_b,  const float* __restrict__ skip_b,
    const float* __restrict__ mlp_b1, const float* __restrict__ mlp_b2,
    int l) {
    extern __shared__ unsigned sm[];
    float*    Xf   = (float*)sm;                 // fp32 state
    unsigned* Xh16 = sm + 128 * XSTR;            // fp16 state mirror
    unsigned* U    = Xh16 + 128 * HSTR;          // union: 2x phase-A bufs | W16
    unsigned* W16  = U;                          // MLP: weight panel (128*HSTR)

    const int tid  = threadIdx.x;
    const int lane = tid & 31, wid = tid >> 5;
    const int grp  = lane >> 2, tg = lane & 3;
    const int lrow = lane & 15;                  // ldmatrix tile row
    const int lk4  = (lane >> 4) << 2;           // ldmatrix k-half offset (u32)
    const int wm   = (wid >> 3) * 64;
    const int wni  = wid & 7;
    const int row0 = blockIdx.x * 128;

    float cA[4][4][4];
#pragma unroll
    for (int i = 0; i < 4; i++)
#pragma unroll
        for (int j = 0; j < 4; j++)
#pragma unroll
            for (int q = 0; q < 4; q++) cA[i][j][q] = 0.f;

    // ---- phase A: feats[128,512] @ W16A[l] -> N=256, fp16 MMA ----
    const int ar = tid >> 2;
    const int aq = tid & 3;
    const int bn = tid & 255;
    const int ko = (tid >> 8) * 16;
    const __half* WA = g_w16A + (size_t)l * 64 * 256 * 8;

    uint4 av, bu[2];
    {
        int gr = row0 + ar;
        av = (gr < N_NODES) ? *(const uint4*)feat16_ptr(gr, aq * 8)
                            : make_uint4(0,0,0,0);
        int c0 = ko >> 3;
        bu[0] = *(const uint4*)(WA + ((size_t)c0 * 256 + bn) * 8);
        bu[1] = *(const uint4*)(WA + ((size_t)(c0 + 1) * 256 + bn) * 8);
    }

    const int wnA = wni * 32;
    for (int k0 = 0; k0 < 512; k0 += 32) {
        unsigned* A16 = U + ((k0 >> 5) & 1) * ABUF;
        unsigned* B16 = A16 + 128 * CSTR;
        *(uint4*)&A16[ar * CSTR + aq * 4] = av;
        *(uint4*)&B16[bn * CSTR + (ko >> 1)]     = bu[0];
        *(uint4*)&B16[bn * CSTR + (ko >> 1) + 4] = bu[1];
        __syncthreads();
        if (k0 + 32 < 512) {
            int kn = k0 + 32;
            int gr = row0 + ar;
            av = (gr < N_NODES) ? *(const uint4*)feat16_ptr(gr, kn + aq * 8)
                                : make_uint4(0,0,0,0);
            int cn = (kn + ko) >> 3;
            bu[0] = *(const uint4*)(WA + ((size_t)cn * 256 + bn) * 8);
            bu[1] = *(const uint4*)(WA + ((size_t)(cn + 1) * 256 + bn) * 8);
        }
#pragma unroll
        for (int s = 0; s < 2; s++) {
            const int sb = s * 8;
            unsigned bq[2][4];
            ldsm4(bq[0], &B16[(wnA + lrow) * CSTR + sb + lk4]);
            ldsm4(bq[1], &B16[(wnA + 16 + lrow) * CSTR + sb + lk4]);
#pragma unroll
            for (int mf = 0; mf < 4; mf++) {
                unsigned ah[4];
                ldsm4(ah, &A16[(wm + mf * 16 + lrow) * CSTR + sb + lk4]);
                MMA_F16(cA[mf][0], ah, bq[0][0], bq[0][2]);
                MMA_F16(cA[mf][1], ah, bq[0][1], bq[0][3]);
                MMA_F16(cA[mf][2], ah, bq[1][0], bq[1][2]);
                MMA_F16(cA[mf][3], ah, bq[1][1], bq[1][3]);
            }
        }
    }

    // phase A epilogue: wni<4 -> h (silu) into Xf/Xh16; wni>=4 -> gskip
    {
        const float* bias = (wni < 4) ? (in_b + l * 128) : (skip_b + l * 128);
#pragma unroll
        for (int mf = 0; mf < 4; mf++) {
            int r0 = wm + mf * 16 + grp;
#pragma unroll
            for (int nf = 0; nf < 4; nf++) {
                int col = (wni & 3) * 32 + nf * 8 + 2 * tg;
                float b0 = bias[col], b1 = bias[col + 1];
                float v0 = cA[mf][nf][0] + b0, v1 = cA[mf][nf][1] + b1;
                float v2 = cA[mf][nf][2] + b0, v3 = cA[mf][nf][3] + b1;
                if (wni < 4) {
                    v0 = silu(v0); v1 = silu(v1); v2 = silu(v2); v3 = silu(v3);
                    int h2 = (col >> 1);
                    Xf[r0*XSTR + col]       = v0; Xf[r0*XSTR + col + 1]   = v1;
                    Xf[(r0+8)*XSTR + col]   = v2; Xf[(r0+8)*XSTR + col+1] = v3;
                    Xh16[r0*HSTR + h2]      = pack_half2(v0, v1);
                    Xh16[(r0+8)*HSTR + h2]  = pack_half2(v2, v3);
                } else {
                    int gr0 = row0 + r0, gr1 = gr0 + 8;
                    if (gr0 < N_NODES) { g_gskip[(size_t)gr0*128 + col] = v0; g_gskip[(size_t)gr0*128 + col+1] = v1; }
                    if (gr1 < N_NODES) { g_gskip[(size_t)gr1*128 + col] = v2; g_gskip[(size_t)gr1*128 + col+1] = v3; }
                }
            }
        }
    }
    __syncthreads();   // phase-A done before W16 overwrites U

    // ---- MLP chain: 2 blocks x 2 phases, K=128, fp16 W panel (interleaved) --
    const int wnM  = wni * 16;
    const int colW = tid & 127;
    const int kseg = (tid >> 7) * 32;

    for (int m = 0; m < 2; m++) {
        const float* B1 = mlp_b1 + (l * 2 + m) * 128;
        const float* B2 = mlp_b2 + (l * 2 + m) * 128;

        for (int phase = 0; phase < 2; phase++) {
            const __half* Wp = g_w16M + (size_t)(((l * 2 + m) * 2) + phase) * 16 * 128 * 8;

#pragma unroll
            for (int j = 0; j < 4; j++)
                *(uint4*)&W16[colW * HSTR + (kseg >> 1) + j * 4] =
                    *(const uint4*)(Wp + ((size_t)((kseg >> 3) + j) * 128 + colW) * 8);
            __syncthreads();

            float cT[4][2][4];
#pragma unroll
            for (int i = 0; i < 4; i++)
#pragma unroll
                for (int j = 0; j < 2; j++)
#pragma unroll
                    for (int q = 0; q < 4; q++) cT[i][j][q] = 0.f;

#pragma unroll
            for (int c = 0; c < 8; c++) {       // 8 x k16 steps, barrier-free
                const int cb = c * 8;
                unsigned bq[4];
                ldsm4(bq, &W16[(wnM + lrow) * HSTR + cb + lk4]);
#pragma unroll
                for (int mf = 0; mf < 4; mf++) {
                    unsigned ah[4];
                    ldsm4(ah, &Xh16[(wm + mf * 16 + lrow) * HSTR + cb + lk4]);
                    MMA_F16(cT[mf][0], ah, bq[0], bq[2]);
                    MMA_F16(cT[mf][1], ah, bq[1], bq[3]);
                }
            }

            if (phase == 0) {
                float res[4][2][4];
#pragma unroll
                for (int mf = 0; mf < 4; mf++) {
                    int r0 = wm + mf * 16 + grp;
#pragma unroll
                    for (int nf = 0; nf < 2; nf++) {
                        int col = wnM + nf * 8 + 2 * tg;
                        res[mf][nf][0] = Xf[r0*XSTR + col];
                        res[mf][nf][1] = Xf[r0*XSTR + col + 1];
                        res[mf][nf][2] = Xf[(r0+8)*XSTR + col];
                        res[mf][nf][3] = Xf[(r0+8)*XSTR + col + 1];
                        cT[mf][nf][0] = silu(cT[mf][nf][0] + B1[col]);
                        cT[mf][nf][1] = silu(cT[mf][nf][1] + B1[col + 1]);
                        cT[mf][nf][2] = silu(cT[mf][nf][2] + B1[col]);
                        cT[mf][nf][3] = silu(cT[mf][nf][3] + B1[col + 1]);
                    }
                }
                __syncthreads();   // Xh16 MMA reads done before overwrite
#pragma unroll
                for (int mf = 0; mf < 4; mf++) {
                    int r0 = wm + mf * 16 + grp;
#pragma unroll
                    for (int nf = 0; nf < 2; nf++) {
                        int col = wnM + nf * 8 + 2 * tg;
                        int h2 = col >> 1;
                        Xf[r0*XSTR+col]       = cT[mf][nf][0]; Xf[r0*XSTR+col+1]     = cT[mf][nf][1];
                        Xf[(r0+8)*XSTR+col]   = cT[mf][nf][2]; Xf[(r0+8)*XSTR+col+1] = cT[mf][nf][3];
                        Xh16[r0*HSTR + h2]     = pack_half2(cT[mf][nf][0], cT[mf][nf][1]);
                        Xh16[(r0+8)*HSTR + h2] = pack_half2(cT[mf][nf][2], cT[mf][nf][3]);
                        cA[mf][nf][0] = res[mf][nf][0]; cA[mf][nf][1] = res[mf][nf][1];
                        cA[mf][nf][2] = res[mf][nf][2]; cA[mf][nf][3] = res[mf][nf][3];
                    }
                }
                __syncthreads();
            } else {
                if (m == 0) __syncthreads();   // Xh16 reads done before overwrite
#pragma unroll
                for (int mf = 0; mf < 4; mf++) {
                    int r0 = wm + mf * 16 + grp;
#pragma unroll
                    for (int nf = 0; nf < 2; nf++) {
                        int col = wnM + nf * 8 + 2 * tg;
                        float o0 = cT[mf][nf][0] + B2[col]     + cA[mf][nf][0];
                        float o1 = cT[mf][nf][1] + B2[col + 1] + cA[mf][nf][1];
                        float o2 = cT[mf][nf][2] + B2[col]     + cA[mf][nf][2];
                        float o3 = cT[mf][nf][3] + B2[col + 1] + cA[mf][nf][3];
                        if (m == 1) {
                            int gr0 = row0 + r0, gr1 = gr0 + 8;
                            if (gr0 < N_NODES) {
                                float f0 = o0 + g_gskip[(size_t)gr0*128 + col];
                                float f1 = o1 + g_gskip[(size_t)gr0*128 + col+1];
                                g_x[(size_t)gr0*128 + col]   = f0;
                                g_x[(size_t)gr0*128 + col+1] = f1;
                                *(unsigned*)&g_xh[(size_t)gr0*128 + col] = pack_half2(f0, f1);
                            }
                            if (gr1 < N_NODES) {
                                float f2 = o2 + g_gskip[(size_t)gr1*128 + col];
                                float f3 = o3 + g_gskip[(size_t)gr1*128 + col+1];
                                g_x[(size_t)gr1*128 + col]   = f2;
                                g_x[(size_t)gr1*128 + col+1] = f3;
                                *(unsigned*)&g_xh[(size_t)gr1*128 + col] = pack_half2(f2, f3);
                            }
                        } else {
                            int h2 = col >> 1;
                            Xf[r0*XSTR+col]       = o0; Xf[r0*XSTR+col+1]     = o1;
                            Xf[(r0+8)*XSTR+col]   = o2; Xf[(r0+8)*XSTR+col+1] = o3;
                            Xh16[r0*HSTR + h2]     = pack_half2(o0, o1);
                            Xh16[(r0+8)*HSTR + h2] = pack_half2(o2, o3);
                        }
                    }
                }
                if (m == 0) __syncthreads();
            }
        }
    }
}

// ================= fused pooling + FFN: one block per graph =================
__global__ __launch_bounds__(128) void pool_ffn_kernel(
    const int* __restrict__ batch,
    const float* __restrict__ attn_w, const float* __restrict__ attn_b,
    const float* __restrict__ temp,
    const float* __restrict__ w1, const float* __restrict__ b1,
    const float* __restrict__ w2, const float* __restrict__ b2,
    const float* __restrict__ w3, const float* __restrict__ b3,
    float* __restrict__ out) {
    const int g = blockIdx.x, t = threadIdx.x;
    const int lane = t & 31, wrp = t >> 5;
    __shared__ int sbeg, send;
    __shared__ float aw[512];
    __shared__ float P[4][128];
    __shared__ float ex[128][4];
    __shared__ float m[4], s[4], rs[4];
    __shared__ float wred[4][4];
    __shared__ float p[128], h1[128], red[128];

    if (t == 0) {
        int lo = 0, hi = N_NODES;
        while (lo < hi) { int mid = (lo + hi) >> 1; if (batch[mid] < g) lo = mid + 1; else hi = mid; }
        sbeg = lo;
        hi = N_NODES;
        while (lo < hi) { int mid = (lo + hi) >> 1; if (batch[mid] < g + 1) lo = mid + 1; else hi = mid; }
        send = lo;
    }
    aw[t] = attn_w[t]; aw[128 + t] = attn_w[128 + t];
    aw[256 + t] = attn_w[256 + t]; aw[384 + t] = attn_w[384 + t];
    if (t < 4) { m[t] = -1e30f; s[t] = 0.f; }
    P[0][t] = 0.f; P[1][t] = 0.f; P[2][t] = 0.f; P[3][t] = 0.f;
    __syncthreads();
    const int beg = sbeg, end = send;
    const float invT = 1.f / temp[0];

    for (int c0 = beg; c0 < end; c0 += 128) {
        int idx = c0 + t;
        bool active = idx < end;
        float sc[4] = {-1e30f, -1e30f, -1e30f, -1e30f};
        if (active) {
            const float* xr = g_x + (size_t)idx * HID;
            float a0 = 0.f, a1 = 0.f, a2 = 0.f, a3 = 0.f;
#pragma unroll 8
            for (int k = 0; k < 128; k += 4) {
                float4 xv = *(const float4*)(xr + k);
                a0 += xv.x*aw[k]     + xv.y*aw[k+1]     + xv.z*aw[k+2]     + xv.w*aw[k+3];
                a1 += xv.x*aw[128+k] + xv.y*aw[128+k+1] + xv.z*aw[128+k+2] + xv.w*aw[128+k+3];
                a2 += xv.x*aw[256+k] + xv.y*aw[256+k+1] + xv.z*aw[256+k+2] + xv.w*aw[256+k+3];
                a3 += xv.x*aw[384+k] + xv.y*aw[384+k+1] + xv.z*aw[384+k+2] + xv.w*aw[384+k+3];
            }
            sc[0] = (a0 + attn_b[0]) * invT;
            sc[1] = (a1 + attn_b[1]) * invT;
            sc[2] = (a2 + attn_b[2]) * invT;
            sc[3] = (a3 + attn_b[3]) * invT;
        }
        float mx[4] = {sc[0], sc[1], sc[2], sc[3]};
#pragma unroll
        for (int o = 16; o; o >>= 1)
#pragma unroll
            for (int h = 0; h < 4; h++) mx[h] = fmaxf(mx[h], __shfl_xor_sync(0xffffffffu, mx[h], o));
        if (lane == 0)
#pragma unroll
            for (int h = 0; h < 4; h++) wred[wrp][h] = mx[h];
        __syncthreads();
        if (t < 4) {
            float cm = fmaxf(fmaxf(wred[0][t], wred[1][t]), fmaxf(wred[2][t], wred[3][t]));
            float nm = fmaxf(m[t], cm);
            rs[t] = __expf(m[t] - nm);
            m[t] = nm;
            s[t] *= rs[t];
        }
        __syncthreads();
        float e[4];
#pragma unroll
        for (int h = 0; h < 4; h++) {
            e[h] = active ? __expf(sc[h] - m[h]) : 0.f;
            ex[t][h] = e[h];
        }
        float sm2[4] = {e[0], e[1], e[2], e[3]};
#pragma unroll
        for (int o = 16; o; o >>= 1)
#pragma unroll
            for (int h = 0; h < 4; h++) sm2[h] += __shfl_xor_sync(0xffffffffu, sm2[h], o);
        if (lane == 0)
#pragma unroll
            for (int h = 0; h < 4; h++) wred[wrp][h] = sm2[h];
        __syncthreads();
        if (t < 4) s[t] += wred[0][t] + wred[1][t] + wred[2][t] + wred[3][t];

        int cnt = min(128, end - c0);
        float p0 = P[0][t] * rs[0], p1 = P[1][t] * rs[1];
        float p2 = P[2][t] * rs[2], p3 = P[3][t] * rs[3];
        for (int n = 0; n < cnt; n++) {
            float xv = g_x[(size_t)(c0 + n) * HID + t];
            p0 += ex[n][0] * xv;
            p1 += ex[n][1] * xv;
            p2 += ex[n][2] * xv;
            p3 += ex[n][3] * xv;
        }
        P[0][t] = p0; P[1][t] = p1; P[2][t] = p2; P[3][t] = p3;
        __syncthreads();
    }

    float pooled = 0.f;
#pragma unroll
    for (int h = 0; h < 4; h++) if (s[h] > 0.f) pooled += P[h][t] / s[h];
    p[t] = pooled * 0.25f;
    __syncthreads();

    float acc = b1[t];
#pragma unroll 8
    for (int k = 0; k < 128; k++) acc += p[k] * w1[k * 128 + t];
    h1[t] = silu(acc);
    __syncthreads();
    float acc2 = b2[t];
#pragma unroll 8
    for (int k = 0; k < 128; k++) acc2 += h1[k] * w2[k * 128 + t];
    acc2 = silu(acc2);
    red[t] = acc2 * w3[t];
    __syncthreads();
    for (int o = 64; o > 0; o >>= 1) {
        if (t < o) red[t] += red[t + o];
        __syncthreads();
    }
    if (t == 0) out[g] = red[0] + b3[0];
}

// ---------------- host launcher ---------------------------------------------
extern "C" void kernel_launch(void* const* d_in, const int* in_sizes, int n_in,
                              void* d_out, int out_size) {
    const int* atom  = (const int*)d_in[0];
    const int* hyd   = (const int*)d_in[1];
    const int* deg   = (const int*)d_in[2];
    const int* hyb   = (const int*)d_in[3];
    const int* tgt   = (const int*)d_in[4];
    const int* srcv  = (const int*)d_in[5];
    const int* batch = (const int*)d_in[6];
    const float* emb_atom = (const float*)d_in[7];
    const float* emb_h    = (const float*)d_in[8];
    const float* emb_deg  = (const float*)d_in[9];
    const float* emb_hyb  = (const float*)d_in[10];
    const float* proj_w   = (const float*)d_in[11];
    const float* proj_b   = (const float*)d_in[12];
    const float* in_w     = (const float*)d_in[13];
    const float* in_b     = (const float*)d_in[14];
    const float* mlp_w1   = (const float*)d_in[15];
    const float* mlp_b1   = (const float*)d_in[16];
    const float* mlp_w2   = (const float*)d_in[17];
    const float* mlp_b2   = (const float*)d_in[18];
    const float* skip_w   = (const float*)d_in[19];
    const float* skip_b   = (const float*)d_in[20];
    const float* attn_w   = (const float*)d_in[21];
    const float* attn_b   = (const float*)d_in[22];
    const float* temp     = (const float*)d_in[23];
    const float* ffn_w1   = (const float*)d_in[24];
    const float* ffn_b1   = (const float*)d_in[25];
    const float* ffn_w2   = (const float*)d_in[26];
    const float* ffn_b2   = (const float*)d_in[27];
    const float* ffn_w3   = (const float*)d_in[28];
    const float* ffn_b3   = (const float*)d_in[29];
    float* out = (float*)d_out;

    const int UNION_U32 = (2 * ABUF) > (128 * HSTR) ? (2 * ABUF) : (128 * HSTR);
    const int LAYER_SMEM = (128 * XSTR + 128 * HSTR + UNION_U32) * 4;
    cudaFuncSetAttribute(layer_kernel, cudaFuncAttributeMaxDynamicSharedMemorySize, LAYER_SMEM);

    // 0a. weight pre-conversion (single launch)
    convert_w_kernel<<<(NWA + NWM + 255) / 256, 256>>>(in_w, skip_w, mlp_w1, mlp_w2);

    // 0b. CSR build (g_cnt arrives zeroed: static init on first call,
    //     reset inside scan_within on every call thereafter)
    count_kernel<<<(N_EDGES + 255) / 256, 256>>>(tgt);
    chunk_sum_kernel<<<NCHUNK, 256>>>();
    scan_chunks_kernel<<<1, 256>>>();
    scan_within_kernel<<<NCHUNK, 1024>>>();
    fill_kernel<<<(N_EDGES + 255) / 256, 256>>>(tgt, srcv);

    // 1. fused embedding + projection (writes fp32 x + fp16 mirror)
    proj_kernel<<<GEMM_BLKS, 256>>>(atom, hyd, deg, hyb, emb_atom, emb_h, emb_deg, emb_hyb,
                                    proj_w, proj_b);

    // 2. shell conv layers
    for (int l = 0; l < 3; l++) {
        gather_hops_kernel<<<(NSLOT * 32 + 255) / 256, 256>>>();
        layer_kernel<<<GEMM_BLKS, 512, LAYER_SMEM>>>(in_b, skip_b, mlp_b1, mlp_b2, l);
    }

    // 3. fused attention pooling + FFN readout
    pool_ffn_kernel<<<NUM_GRAPHS, 128>>>(batch, attn_w, attn_b, temp,
                                         ffn_w1, ffn_b1, ffn_w2, ffn_b2, ffn_w3, ffn_b3, out);
}

// round 15
// speedup vs baseline: 1.1786x; 1.1786x over previous
#include <cuda_runtime.h>
#include <cuda_fp16.h>

#define N_NODES   50000
#define N_EDGES   2400000
#define NUM_GRAPHS 2048
#define NSLOT     (3 * N_NODES)          // 150000 hop-slots
#define NCHUNK    ((NSLOT + 1023) / 1024) // 147
#define HID       128
#define GEMM_BLKS ((N_NODES + 127) / 128)   // 391
#define ASTR 20    // smem stride for proj streamed tiles (tf32 path)
#define XSTR 132   // smem stride (u32) for resident fp32 state
#define HSTR 68    // smem stride (u32) for resident fp16 buffers
#define CSTR 20    // smem stride (u32) for streamed fp16 chunks
#define ABUF (128 * CSTR + 256 * CSTR)   // one phase-A buffer (u32)
#define NWA  (3 * 512 * 256)             // phase-A weight elements
#define NWM  (3 * 2 * 2 * 128 * 128)     // MLP weight elements

// ---------------- scratch (static device memory; no allocs) ----------------
__device__ __align__(16) float  g_x[N_NODES * HID];
__device__ __align__(16) __half g_xh[N_NODES * HID];             // fp16 mirror of x
__device__ __align__(16) __half g_hops16[(size_t)N_NODES * 384]; // fp16 hop sums
__device__ __align__(16) float  g_gskip[N_NODES * HID];
// interleaved fp16 weights: [kc][n][8] tiles (kc = k/8) -> coalesced uint4 loads
__device__ __align__(16) __half g_w16A[3 * 64 * 256 * 8];        // phase A: [l][kc][n][8]
__device__ __align__(16) __half g_w16M[3 * 2 * 2 * 16 * 128 * 8];// MLP: [lm][ph][kc][n][8]
__device__ int g_cnt[NSLOT];             // zero-init; reset each launch by scan_within
__device__ int g_csum[NCHUNK];
__device__ int g_coff[NCHUNK];
__device__ int g_rowptr[NSLOT + 1];
__device__ int g_cursor[NSLOT];
__device__ int g_esrc[N_EDGES];

__device__ __forceinline__ float silu(float v) { return v / (1.f + __expf(-v)); }

__device__ __forceinline__ unsigned f2tf32(float v) {
    unsigned r;
    asm("cvt.rna.tf32.f32 %0, %1;" : "=r"(r) : "f"(v));
    return r;
}
__device__ __forceinline__ unsigned pack_half2(float a, float b) {
    __half2 h = __floats2half2_rn(a, b);
    return *(unsigned*)&h;
}
__device__ __forceinline__ void ldsm4(unsigned r[4], const unsigned* p) {
    unsigned a = (unsigned)__cvta_generic_to_shared(p);
    asm volatile("ldmatrix.sync.aligned.m8n8.x4.shared.b16 {%0,%1,%2,%3}, [%4];"
                 : "=r"(r[0]), "=r"(r[1]), "=r"(r[2]), "=r"(r[3]) : "r"(a));
}

#define MMA_TF32(cc, aa, bb) \
    asm volatile("mma.sync.aligned.m16n8k8.row.col.f32.tf32.tf32.f32 " \
                 "{%0,%1,%2,%3},{%4,%5,%6,%7},{%8,%9},{%0,%1,%2,%3};" \
                 : "+f"(cc[0]), "+f"(cc[1]), "+f"(cc[2]), "+f"(cc[3]) \
                 : "r"(aa[0]), "r"(aa[1]), "r"(aa[2]), "r"(aa[3]), \
                   "r"(bb[0]), "r"(bb[1]))

#define MMA_F16(cc, aa, b0v, b1v) \
    asm volatile("mma.sync.aligned.m16n8k16.row.col.f32.f16.f16.f32 " \
                 "{%0,%1,%2,%3},{%4,%5,%6,%7},{%8,%9},{%0,%1,%2,%3};" \
                 : "+f"(cc[0]), "+f"(cc[1]), "+f"(cc[2]), "+f"(cc[3]) \
                 : "r"(aa[0]), "r"(aa[1]), "r"(aa[2]), "r"(aa[3]), \
                   "r"(b0v), "r"(b1v))

// ========= weight pre-conversion to interleaved fp16 [kc][n][8] (one launch) =
__global__ void convert_w_kernel(const float* __restrict__ in_w,
                                 const float* __restrict__ skip_w,
                                 const float* __restrict__ w1,
                                 const float* __restrict__ w2) {
    int idx = blockIdx.x * blockDim.x + threadIdx.x;
    if (idx < NWA) {
        int l = idx / (512 * 256);
        int rem = idx % (512 * 256);
        int k = rem >> 8;
        int n = rem & 255;
        const float* src = (n < 128) ? in_w : skip_w;
        float v = src[(size_t)l * 512 * 128 + (size_t)k * 128 + (n & 127)];
        size_t dst = (((size_t)l * 64 + (k >> 3)) * 256 + n) * 8 + (k & 7);
        g_w16A[dst] = __float2half(v);
    } else if (idx < NWA + NWM) {
        int j = idx - NWA;
        int panel = j >> 14;
        int rem = j & 0x3FFF;
        int k = rem >> 7;
        int n = rem & 127;
        int phase = panel & 1;
        int lm = panel >> 1;
        const float* src = phase ? w2 : w1;
        float v = src[(size_t)lm * 16384 + (size_t)k * 128 + n];
        size_t dst = (((size_t)panel * 16 + (k >> 3)) * 128 + n) * 8 + (k & 7);
        g_w16M[dst] = __float2half(v);
    }
}

// ================= CSR build =================
__global__ void count_kernel(const int* __restrict__ tgt) {
    int e = blockIdx.x * blockDim.x + threadIdx.x;
    if (e < N_EDGES) atomicAdd(&g_cnt[tgt[e]], 1);
}
__global__ void chunk_sum_kernel() {
    __shared__ int red[256];
    int b = blockIdx.x, t = threadIdx.x;
    int s = 0;
#pragma unroll
    for (int j = 0; j < 4; j++) {
        int i = b * 1024 + j * 256 + t;
        if (i < NSLOT) s += g_cnt[i];
    }
    red[t] = s; __syncthreads();
    for (int o = 128; o > 0; o >>= 1) {
        if (t < o) red[t] += red[t + o];
        __syncthreads();
    }
    if (t == 0) g_csum[b] = red[0];
}
__global__ void scan_chunks_kernel() {
    __shared__ int buf[2][256];
    int t = threadIdx.x;
    int v = (t < NCHUNK) ? g_csum[t] : 0;
    buf[0][t] = v;
    __syncthreads();
    int cur = 0;
#pragma unroll
    for (int off = 1; off < 256; off <<= 1) {
        int nv = buf[cur][t] + ((t >= off) ? buf[cur][t - off] : 0);
        buf[cur ^ 1][t] = nv;
        cur ^= 1;
        __syncthreads();
    }
    if (t < NCHUNK) g_coff[t] = buf[cur][t] - v;
    if (t == NCHUNK - 1) g_rowptr[NSLOT] = buf[cur][t];
}
__global__ void scan_within_kernel() {
    __shared__ int buf[2][1024];
    int b = blockIdx.x, t = threadIdx.x;
    int i = b * 1024 + t;
    int v = (i < NSLOT) ? g_cnt[i] : 0;
    buf[0][t] = v;
    __syncthreads();
    int cur = 0;
#pragma unroll
    for (int off = 1; off < 1024; off <<= 1) {
        int nv = buf[cur][t] + ((t >= off) ? buf[cur][t - off] : 0);
        buf[cur ^ 1][t] = nv;
        cur ^= 1;
        __syncthreads();
    }
    if (i < NSLOT) {
        int excl = buf[cur][t] - v;
        int rp = g_coff[b] + excl;
        g_rowptr[i] = rp;
        g_cursor[i] = rp;
        g_cnt[i] = 0;   // reset for next launch (graph replay)
    }
}
__global__ void fill_kernel(const int* __restrict__ tgt, const int* __restrict__ srcv) {
    int e = blockIdx.x * blockDim.x + threadIdx.x;
    if (e >= N_EDGES) return;
    int t = tgt[e];
    int pos = atomicAdd(&g_cursor[t], 1);
    g_esrc[pos] = srcv[e] % N_NODES;
}

// ================= hop gather: fp16 rows, fp32 accum, 4-way ILP (R13) ========
__global__ __launch_bounds__(256) void gather_hops_kernel() {
    int slot = (blockIdx.x * blockDim.x + threadIdx.x) >> 5;
    int lane = threadIdx.x & 31;
    if (slot >= NSLOT) return;
    int beg = g_rowptr[slot], end = g_rowptr[slot + 1];
    float4 a0 = make_float4(0.f,0.f,0.f,0.f), a1 = a0, a2 = a0, a3 = a0;
    const uint2* xh = (const uint2*)g_xh;
    int e = beg;
    for (; e + 3 < end; e += 4) {
        int s0 = g_esrc[e], s1 = g_esrc[e+1], s2 = g_esrc[e+2], s3 = g_esrc[e+3];
        uint2 u0 = xh[(size_t)s0 * 32 + lane];
        uint2 u1 = xh[(size_t)s1 * 32 + lane];
        uint2 u2 = xh[(size_t)s2 * 32 + lane];
        uint2 u3 = xh[(size_t)s3 * 32 + lane];
        float2 f;
        f = __half22float2(*(__half2*)&u0.x); a0.x += f.x; a0.y += f.y;
        f = __half22float2(*(__half2*)&u0.y); a0.z += f.x; a0.w += f.y;
        f = __half22float2(*(__half2*)&u1.x); a1.x += f.x; a1.y += f.y;
        f = __half22float2(*(__half2*)&u1.y); a1.z += f.x; a1.w += f.y;
        f = __half22float2(*(__half2*)&u2.x); a2.x += f.x; a2.y += f.y;
        f = __half22float2(*(__half2*)&u2.y); a2.z += f.x; a2.w += f.y;
        f = __half22float2(*(__half2*)&u3.x); a3.x += f.x; a3.y += f.y;
        f = __half22float2(*(__half2*)&u3.y); a3.z += f.x; a3.w += f.y;
    }
    for (; e < end; e++) {
        int s0 = g_esrc[e];
        uint2 u0 = xh[(size_t)s0 * 32 + lane];
        float2 f;
        f = __half22float2(*(__half2*)&u0.x); a0.x += f.x; a0.y += f.y;
        f = __half22float2(*(__half2*)&u0.y); a0.z += f.x; a0.w += f.y;
    }
    a0.x += a1.x + a2.x + a3.x;
    a0.y += a1.y + a2.y + a3.y;
    a0.z += a1.z + a2.z + a3.z;
    a0.w += a1.w + a2.w + a3.w;
    int node = slot % N_NODES, hop = slot / N_NODES;
    uint2 o;
    o.x = pack_half2(a0.x, a0.y);
    o.y = pack_half2(a0.z, a0.w);
    ((uint2*)g_hops16)[(size_t)node * 96 + hop * 32 + lane] = o;
}

// ================= fused embed+proj GEMM (single-pass tf32) =================
__global__ __launch_bounds__(256) void proj_kernel(
    const int* __restrict__ atom, const int* __restrict__ hyd,
    const int* __restrict__ deg,  const int* __restrict__ hyb,
    const float* __restrict__ ea, const float* __restrict__ eh,
    const float* __restrict__ ed, const float* __restrict__ ey,
    const float* __restrict__ B, const float* __restrict__ bias) {
    __shared__ unsigned Ah[128 * ASTR];
    __shared__ unsigned Bh[128 * ASTR];
    __shared__ int sidx[128][4];

    const int tid  = threadIdx.x;
    const int lane = tid & 31, wid = tid >> 5;
    const int wm = (wid >> 2) * 64;
    const int wn = (wid & 3) * 32;
    const int grp = lane >> 2, tg = lane & 3;
    const int row0 = blockIdx.x * 128;

    if (tid < 128) {
        int gr = row0 + tid;
        int g2 = (gr < N_NODES) ? gr : 0;
        sidx[tid][0] = atom[g2];
        sidx[tid][1] = hyd[g2];
        sidx[tid][2] = deg[g2];
        sidx[tid][3] = hyb[g2];
    }
    __syncthreads();
    const float* tabs[4] = {ea, eh, ed, ey};

    float c[4][4][4];
#pragma unroll
    for (int i = 0; i < 4; i++)
#pragma unroll
        for (int j = 0; j < 4; j++)
#pragma unroll
            for (int q = 0; q < 4; q++) c[i][j][q] = 0.f;

    const int ar  = tid >> 2;
    const int ac4 = (tid & 3) * 4;
    const int bn  = tid & 127;
    const int bk0 = (tid >> 7) * 8;

    for (int k0 = 0; k0 < 256; k0 += 16) {
        float4 av[2]; float bv[8];
        int kt = (k0 + ac4) >> 6, kw = (k0 + ac4) & 63;
#pragma unroll
        for (int it = 0; it < 2; it++) {
            int r = ar + it * 64;
            av[it] = *(const float4*)(tabs[kt] + (size_t)sidx[r][kt] * 64 + kw);
        }
#pragma unroll
        for (int kk = 0; kk < 8; kk++) bv[kk] = B[(size_t)(k0 + bk0 + kk) * 128 + bn];

        __syncthreads();
#pragma unroll
        for (int it = 0; it < 2; it++) {
            int r = ar + it * 64;
            float vv[4] = {av[it].x, av[it].y, av[it].z, av[it].w};
#pragma unroll
            for (int j = 0; j < 4; j++) Ah[r * ASTR + ac4 + j] = f2tf32(vv[j]);
        }
#pragma unroll
        for (int kk = 0; kk < 8; kk++) Bh[bn * ASTR + bk0 + kk] = f2tf32(bv[kk]);
        __syncthreads();
#pragma unroll
        for (int s = 0; s < 2; s++) {
            const int ks = s * 8;
            unsigned bh[4][2];
#pragma unroll
            for (int nf = 0; nf < 4; nf++) {
                int b0 = (wn + nf * 8 + grp) * ASTR + ks + tg;
                bh[nf][0] = Bh[b0]; bh[nf][1] = Bh[b0 + 4];
            }
#pragma unroll
            for (int mf = 0; mf < 4; mf++) {
                unsigned ah[4];
                int a0 = (wm + mf * 16 + grp) * ASTR + ks + tg;
                int a1 = a0 + 8 * ASTR;
                ah[0] = Ah[a0]; ah[1] = Ah[a1]; ah[2] = Ah[a0 + 4]; ah[3] = Ah[a1 + 4];
#pragma unroll
                for (int nf = 0; nf < 4; nf++) MMA_TF32(c[mf][nf], ah, bh[nf]);
            }
        }
    }

#pragma unroll
    for (int mf = 0; mf < 4; mf++) {
        int r0 = row0 + wm + mf * 16 + grp;
        int r1 = r0 + 8;
#pragma unroll
        for (int nf = 0; nf < 4; nf++) {
            int col = wn + nf * 8 + 2 * tg;
            float bia0 = bias[col], bia1 = bias[col + 1];
            if (r0 < N_NODES) {
                float v0 = silu(c[mf][nf][0] + bia0), v1 = silu(c[mf][nf][1] + bia1);
                g_x[(size_t)r0 * 128 + col]     = v0;
                g_x[(size_t)r0 * 128 + col + 1] = v1;
                *(unsigned*)&g_xh[(size_t)r0 * 128 + col] = pack_half2(v0, v1);
            }
            if (r1 < N_NODES) {
                float v2 = silu(c[mf][nf][2] + bia0), v3 = silu(c[mf][nf][3] + bia1);
                g_x[(size_t)r1 * 128 + col]     = v2;
                g_x[(size_t)r1 * 128 + col + 1] = v3;
                *(unsigned*)&g_xh[(size_t)r1 * 128 + col] = pack_half2(v2, v3);
            }
        }
    }
}

// ================= mega layer kernel (fp16 MMA via ldmatrix) =================
__device__ __forceinline__ const __half* feat16_ptr(int gr, int k) {
    return (k < 128) ? (g_xh + (size_t)gr * 128 + k)
                     : (g_hops16 + (size_t)gr * 384 + (k - 128));
}

__global__ __launch_bounds__(512, 1) void layer_kernel(
    const float* __restrict__ in_b,  const float* __restrict__ skip_b,
    const float* __restrict__ mlp_b1, const float* __restrict__ mlp_b2,
    int l) {
    extern __shared__ unsigned sm[];
    float*    Xf   = (float*)sm;                 // fp32 state
    unsigned* Xh16 = sm + 128 * XSTR;            // fp16 state mirror
    unsigned* U    = Xh16 + 128 * HSTR;          // union: 2x phase-A bufs | W16
    unsigned* W16  = U;                          // MLP: weight panel (128*HSTR)

    const int tid  = threadIdx.x;
    const int lane = tid & 31, wid = tid >> 5;
    const int grp  = lane >> 2, tg = lane & 3;
    const int lrow = lane & 15;                  // ldmatrix tile row
    const int lk4  = (lane >> 4) << 2;           // ldmatrix k-half offset (u32)
    const int wm   = (wid >> 3) * 64;
    const int wni  = wid & 7;
    const int row0 = blockIdx.x * 128;

    float cA[4][4][4];
#pragma unroll
    for (int i = 0; i < 4; i++)
#pragma unroll
        for (int j = 0; j < 4; j++)
#pragma unroll
            for (int q = 0; q < 4; q++) cA[i][j][q] = 0.f;

    // ---- phase A: feats[128,512] @ W16A[l] -> N=256, fp16 MMA ----
    const int ar = tid >> 2;
    const int aq = tid & 3;
    const int bn = tid & 255;
    const int ko = (tid >> 8) * 16;
    const __half* WA = g_w16A + (size_t)l * 64 * 256 * 8;

    uint4 av, bu[2];
    {
        int gr = row0 + ar;
        av = (gr < N_NODES) ? *(const uint4*)feat16_ptr(gr, aq * 8)
                            : make_uint4(0,0,0,0);
        int c0 = ko >> 3;
        bu[0] = *(const uint4*)(WA + ((size_t)c0 * 256 + bn) * 8);
        bu[1] = *(const uint4*)(WA + ((size_t)(c0 + 1) * 256 + bn) * 8);
    }

    const int wnA = wni * 32;
    for (int k0 = 0; k0 < 512; k0 += 32) {
        unsigned* A16 = U + ((k0 >> 5) & 1) * ABUF;
        unsigned* B16 = A16 + 128 * CSTR;
        *(uint4*)&A16[ar * CSTR + aq * 4] = av;
        *(uint4*)&B16[bn * CSTR + (ko >> 1)]     = bu[0];
        *(uint4*)&B16[bn * CSTR + (ko >> 1) + 4] = bu[1];
        __syncthreads();
        if (k0 + 32 < 512) {
            int kn = k0 + 32;
            int gr = row0 + ar;
            av = (gr < N_NODES) ? *(const uint4*)feat16_ptr(gr, kn + aq * 8)
                                : make_uint4(0,0,0,0);
            int cn = (kn + ko) >> 3;
            bu[0] = *(const uint4*)(WA + ((size_t)cn * 256 + bn) * 8);
            bu[1] = *(const uint4*)(WA + ((size_t)(cn + 1) * 256 + bn) * 8);
        }
#pragma unroll
        for (int s = 0; s < 2; s++) {
            const int sb = s * 8;
            unsigned bq[2][4];
            ldsm4(bq[0], &B16[(wnA + lrow) * CSTR + sb + lk4]);
            ldsm4(bq[1], &B16[(wnA + 16 + lrow) * CSTR + sb + lk4]);
#pragma unroll
            for (int mf = 0; mf < 4; mf++) {
                unsigned ah[4];
                ldsm4(ah, &A16[(wm + mf * 16 + lrow) * CSTR + sb + lk4]);
                MMA_F16(cA[mf][0], ah, bq[0][0], bq[0][2]);
                MMA_F16(cA[mf][1], ah, bq[0][1], bq[0][3]);
                MMA_F16(cA[mf][2], ah, bq[1][0], bq[1][2]);
                MMA_F16(cA[mf][3], ah, bq[1][1], bq[1][3]);
            }
        }
    }

    // phase A epilogue: wni<4 -> h (silu) into Xf/Xh16; wni>=4 -> gskip
    {
        const float* bias = (wni < 4) ? (in_b + l * 128) : (skip_b + l * 128);
#pragma unroll
        for (int mf = 0; mf < 4; mf++) {
            int r0 = wm + mf * 16 + grp;
#pragma unroll
            for (int nf = 0; nf < 4; nf++) {
                int col = (wni & 3) * 32 + nf * 8 + 2 * tg;
                float b0 = bias[col], b1 = bias[col + 1];
                float v0 = cA[mf][nf][0] + b0, v1 = cA[mf][nf][1] + b1;
                float v2 = cA[mf][nf][2] + b0, v3 = cA[mf][nf][3] + b1;
                if (wni < 4) {
                    v0 = silu(v0); v1 = silu(v1); v2 = silu(v2); v3 = silu(v3);
                    int h2 = (col >> 1);
                    Xf[r0*XSTR + col]       = v0; Xf[r0*XSTR + col + 1]   = v1;
                    Xf[(r0+8)*XSTR + col]   = v2; Xf[(r0+8)*XSTR + col+1] = v3;
                    Xh16[r0*HSTR + h2]      = pack_half2(v0, v1);
                    Xh16[(r0+8)*HSTR + h2]  = pack_half2(v2, v3);
                } else {
                    int gr0 = row0 + r0, gr1 = gr0 + 8;
                    if (gr0 < N_NODES) { g_gskip[(size_t)gr0*128 + col] = v0; g_gskip[(size_t)gr0*128 + col+1] = v1; }
                    if (gr1 < N_NODES) { g_gskip[(size_t)gr1*128 + col] = v2; g_gskip[(size_t)gr1*128 + col+1] = v3; }
                }
            }
        }
    }
    __syncthreads();   // phase-A done before W16 overwrites U

    // ---- MLP chain: 2 blocks x 2 phases, K=128, fp16 W panel (interleaved) --
    const int wnM  = wni * 16;
    const int colW = tid & 127;
    const int kseg = (tid >> 7) * 32;

    for (int m = 0; m < 2; m++) {
        const float* B1 = mlp_b1 + (l * 2 + m) * 128;
        const float* B2 = mlp_b2 + (l * 2 + m) * 128;

        for (int phase = 0; phase < 2; phase++) {
            const __half* Wp = g_w16M + (size_t)(((l * 2 + m) * 2) + phase) * 16 * 128 * 8;

#pragma unroll
            for (int j = 0; j < 4; j++)
                *(uint4*)&W16[colW * HSTR + (kseg >> 1) + j * 4] =
                    *(const uint4*)(Wp + ((size_t)((kseg >> 3) + j) * 128 + colW) * 8);
            __syncthreads();

            float cT[4][2][4];
#pragma unroll
            for (int i = 0; i < 4; i++)
#pragma unroll
                for (int j = 0; j < 2; j++)
#pragma unroll
                    for (int q = 0; q < 4; q++) cT[i][j][q] = 0.f;

#pragma unroll
            for (int c = 0; c < 8; c++) {       // 8 x k16 steps, barrier-free
                const int cb = c * 8;
                unsigned bq[4];
                ldsm4(bq, &W16[(wnM + lrow) * HSTR + cb + lk4]);
#pragma unroll
                for (int mf = 0; mf < 4; mf++) {
                    unsigned ah[4];
                    ldsm4(ah, &Xh16[(wm + mf * 16 + lrow) * HSTR + cb + lk4]);
                    MMA_F16(cT[mf][0], ah, bq[0], bq[2]);
                    MMA_F16(cT[mf][1], ah, bq[1], bq[3]);
                }
            }

            if (phase == 0) {
                float res[4][2][4];
#pragma unroll
                for (int mf = 0; mf < 4; mf++) {
                    int r0 = wm + mf * 16 + grp;
#pragma unroll
                    for (int nf = 0; nf < 2; nf++) {
                        int col = wnM + nf * 8 + 2 * tg;
                        res[mf][nf][0] = Xf[r0*XSTR + col];
                        res[mf][nf][1] = Xf[r0*XSTR + col + 1];
                        res[mf][nf][2] = Xf[(r0+8)*XSTR + col];
                        res[mf][nf][3] = Xf[(r0+8)*XSTR + col + 1];
                        cT[mf][nf][0] = silu(cT[mf][nf][0] + B1[col]);
                        cT[mf][nf][1] = silu(cT[mf][nf][1] + B1[col + 1]);
                        cT[mf][nf][2] = silu(cT[mf][nf][2] + B1[col]);
                        cT[mf][nf][3] = silu(cT[mf][nf][3] + B1[col + 1]);
                    }
                }
                __syncthreads();   // Xh16 MMA reads done before overwrite
#pragma unroll
                for (int mf = 0; mf < 4; mf++) {
                    int r0 = wm + mf * 16 + grp;
#pragma unroll
                    for (int nf = 0; nf < 2; nf++) {
                        int col = wnM + nf * 8 + 2 * tg;
                        int h2 = col >> 1;
                        Xf[r0*XSTR+col]       = cT[mf][nf][0]; Xf[r0*XSTR+col+1]     = cT[mf][nf][1];
                        Xf[(r0+8)*XSTR+col]   = cT[mf][nf][2]; Xf[(r0+8)*XSTR+col+1] = cT[mf][nf][3];
                        Xh16[r0*HSTR + h2]     = pack_half2(cT[mf][nf][0], cT[mf][nf][1]);
                        Xh16[(r0+8)*HSTR + h2] = pack_half2(cT[mf][nf][2], cT[mf][nf][3]);
                        cA[mf][nf][0] = res[mf][nf][0]; cA[mf][nf][1] = res[mf][nf][1];
                        cA[mf][nf][2] = res[mf][nf][2]; cA[mf][nf][3] = res[mf][nf][3];
                    }
                }
                __syncthreads();
            } else {
                if (m == 0) __syncthreads();   // Xh16 reads done before overwrite
#pragma unroll
                for (int mf = 0; mf < 4; mf++) {
                    int r0 = wm + mf * 16 + grp;
#pragma unroll
                    for (int nf = 0; nf < 2; nf++) {
                        int col = wnM + nf * 8 + 2 * tg;
                        float o0 = cT[mf][nf][0] + B2[col]     + cA[mf][nf][0];
                        float o1 = cT[mf][nf][1] + B2[col + 1] + cA[mf][nf][1];
                        float o2 = cT[mf][nf][2] + B2[col]     + cA[mf][nf][2];
                        float o3 = cT[mf][nf][3] + B2[col + 1] + cA[mf][nf][3];
                        if (m == 1) {
                            int gr0 = row0 + r0, gr1 = gr0 + 8;
                            if (gr0 < N_NODES) {
                                float f0 = o0 + g_gskip[(size_t)gr0*128 + col];
                                float f1 = o1 + g_gskip[(size_t)gr0*128 + col+1];
                                g_x[(size_t)gr0*128 + col]   = f0;
                                g_x[(size_t)gr0*128 + col+1] = f1;
                                *(unsigned*)&g_xh[(size_t)gr0*128 + col] = pack_half2(f0, f1);
                            }
                            if (gr1 < N_NODES) {
                                float f2 = o2 + g_gskip[(size_t)gr1*128 + col];
                                float f3 = o3 + g_gskip[(size_t)gr1*128 + col+1];
                                g_x[(size_t)gr1*128 + col]   = f2;
                                g_x[(size_t)gr1*128 + col+1] = f3;
                                *(unsigned*)&g_xh[(size_t)gr1*128 + col] = pack_half2(f2, f3);
                            }
                        } else {
                            int h2 = col >> 1;
                            Xf[r0*XSTR+col]       = o0; Xf[r0*XSTR+col+1]     = o1;
                            Xf[(r0+8)*XSTR+col]   = o2; Xf[(r0+8)*XSTR+col+1] = o3;
                            Xh16[r0*HSTR + h2]     = pack_half2(o0, o1);
                            Xh16[(r0+8)*HSTR + h2] = pack_half2(o2, o3);
                        }
                    }
                }
                if (m == 0) __syncthreads();
            }
        }
    }
}

// ================= fused pooling + FFN: one block per graph =================
__global__ __launch_bounds__(128) void pool_ffn_kernel(
    const int* __restrict__ batch,
    const float* __restrict__ attn_w, const float* __restrict__ attn_b,
    const float* __restrict__ temp,
    const float* __restrict__ w1, const float* __restrict__ b1,
    const float* __restrict__ w2, const float* __restrict__ b2,
    const float* __restrict__ w3, const float* __restrict__ b3,
    float* __restrict__ out) {
    const int g = blockIdx.x, t = threadIdx.x;
    const int lane = t & 31, wrp = t >> 5;
    __shared__ int sbeg, send;
    __shared__ float aw[512];
    __shared__ float P[4][128];
    __shared__ float ex[128][4];
    __shared__ float m[4], s[4], rs[4];
    __shared__ float wred[4][4];
    __shared__ float p[128], h1[128], red[128];

    if (t == 0) {
        int lo = 0, hi = N_NODES;
        while (lo < hi) { int mid = (lo + hi) >> 1; if (batch[mid] < g) lo = mid + 1; else hi = mid; }
        sbeg = lo;
        hi = N_NODES;
        while (lo < hi) { int mid = (lo + hi) >> 1; if (batch[mid] < g + 1) lo = mid + 1; else hi = mid; }
        send = lo;
    }
    aw[t] = attn_w[t]; aw[128 + t] = attn_w[128 + t];
    aw[256 + t] = attn_w[256 + t]; aw[384 + t] = attn_w[384 + t];
    if (t < 4) { m[t] = -1e30f; s[t] = 0.f; }
    P[0][t] = 0.f; P[1][t] = 0.f; P[2][t] = 0.f; P[3][t] = 0.f;
    __syncthreads();
    const int beg = sbeg, end = send;
    const float invT = 1.f / temp[0];

    for (int c0 = beg; c0 < end; c0 += 128) {
        int idx = c0 + t;
        bool active = idx < end;
        float sc[4] = {-1e30f, -1e30f, -1e30f, -1e30f};
        if (active) {
            const float* xr = g_x + (size_t)idx * HID;
            float a0 = 0.f, a1 = 0.f, a2 = 0.f, a3 = 0.f;
#pragma unroll 8
            for (int k = 0; k < 128; k += 4) {
                float4 xv = *(const float4*)(xr + k);
                a0 += xv.x*aw[k]     + xv.y*aw[k+1]     + xv.z*aw[k+2]     + xv.w*aw[k+3];
                a1 += xv.x*aw[128+k] + xv.y*aw[128+k+1] + xv.z*aw[128+k+2] + xv.w*aw[128+k+3];
                a2 += xv.x*aw[256+k] + xv.y*aw[256+k+1] + xv.z*aw[256+k+2] + xv.w*aw[256+k+3];
                a3 += xv.x*aw[384+k] + xv.y*aw[384+k+1] + xv.z*aw[384+k+2] + xv.w*aw[384+k+3];
            }
            sc[0] = (a0 + attn_b[0]) * invT;
            sc[1] = (a1 + attn_b[1]) * invT;
            sc[2] = (a2 + attn_b[2]) * invT;
            sc[3] = (a3 + attn_b[3]) * invT;
        }
        float mx[4] = {sc[0], sc[1], sc[2], sc[3]};
#pragma unroll
        for (int o = 16; o; o >>= 1)
#pragma unroll
            for (int h = 0; h < 4; h++) mx[h] = fmaxf(mx[h], __shfl_xor_sync(0xffffffffu, mx[h], o));
        if (lane == 0)
#pragma unroll
            for (int h = 0; h < 4; h++) wred[wrp][h] = mx[h];
        __syncthreads();
        if (t < 4) {
            float cm = fmaxf(fmaxf(wred[0][t], wred[1][t]), fmaxf(wred[2][t], wred[3][t]));
            float nm = fmaxf(m[t], cm);
            rs[t] = __expf(m[t] - nm);
            m[t] = nm;
            s[t] *= rs[t];
        }
        __syncthreads();
        float e[4];
#pragma unroll
        for (int h = 0; h < 4; h++) {
            e[h] = active ? __expf(sc[h] - m[h]) : 0.f;
            ex[t][h] = e[h];
        }
        float sm2[4] = {e[0], e[1], e[2], e[3]};
#pragma unroll
        for (int o = 16; o; o >>= 1)
#pragma unroll
            for (int h = 0; h < 4; h++) sm2[h] += __shfl_xor_sync(0xffffffffu, sm2[h], o);
        if (lane == 0)
#pragma unroll
            for (int h = 0; h < 4; h++) wred[wrp][h] = sm2[h];
        __syncthreads();
        if (t < 4) s[t] += wred[0][t] + wred[1][t] + wred[2][t] + wred[3][t];

        int cnt = min(128, end - c0);
        float p0 = P[0][t] * rs[0], p1 = P[1][t] * rs[1];
        float p2 = P[2][t] * rs[2], p3 = P[3][t] * rs[3];
        for (int n = 0; n < cnt; n++) {
            float xv = g_x[(size_t)(c0 + n) * HID + t];
            p0 += ex[n][0] * xv;
            p1 += ex[n][1] * xv;
            p2 += ex[n][2] * xv;
            p3 += ex[n][3] * xv;
        }
        P[0][t] = p0; P[1][t] = p1; P[2][t] = p2; P[3][t] = p3;
        __syncthreads();
    }

    float pooled = 0.f;
#pragma unroll
    for (int h = 0; h < 4; h++) if (s[h] > 0.f) pooled += P[h][t] / s[h];
    p[t] = pooled * 0.25f;
    __syncthreads();

    float acc = b1[t];
#pragma unroll 8
    for (int k = 0; k < 128; k++) acc += p[k] * w1[k * 128 + t];
    h1[t] = silu(acc);
    __syncthreads();
    float acc2 = b2[t];
#pragma unroll 8
    for (int k = 0; k < 128; k++) acc2 += h1[k] * w2[k * 128 + t];
    acc2 = silu(acc2);
    red[t] = acc2 * w3[t];
    __syncthreads();
    for (int o = 64; o > 0; o >>= 1) {
        if (t < o) red[t] += red[t + o];
        __syncthreads();
    }
    if (t == 0) out[g] = red[0] + b3[0];
}

// ---------------- host launcher ---------------------------------------------
extern "C" void kernel_launch(void* const* d_in, const int* in_sizes, int n_in,
                              void* d_out, int out_size) {
    const int* atom  = (const int*)d_in[0];
    const int* hyd   = (const int*)d_in[1];
    const int* deg   = (const int*)d_in[2];
    const int* hyb   = (const int*)d_in[3];
    const int* tgt   = (const int*)d_in[4];
    const int* srcv  = (const int*)d_in[5];
    const int* batch = (const int*)d_in[6];
    const float* emb_atom = (const float*)d_in[7];
    const float* emb_h    = (const float*)d_in[8];
    const float* emb_deg  = (const float*)d_in[9];
    const float* emb_hyb  = (const float*)d_in[10];
    const float* proj_w   = (const float*)d_in[11];
    const float* proj_b   = (const float*)d_in[12];
    const float* in_w     = (const float*)d_in[13];
    const float* in_b     = (const float*)d_in[14];
    const float* mlp_w1   = (const float*)d_in[15];
    const float* mlp_b1   = (const float*)d_in[16];
    const float* mlp_w2   = (const float*)d_in[17];
    const float* mlp_b2   = (const float*)d_in[18];
    const float* skip_w   = (const float*)d_in[19];
    const float* skip_b   = (const float*)d_in[20];
    const float* attn_w   = (const float*)d_in[21];
    const float* attn_b   = (const float*)d_in[22];
    const float* temp     = (const float*)d_in[23];
    const float* ffn_w1   = (const float*)d_in[24];
    const float* ffn_b1   = (const float*)d_in[25];
    const float* ffn_w2   = (const float*)d_in[26];
    const float* ffn_b2   = (const float*)d_in[27];
    const float* ffn_w3   = (const float*)d_in[28];
    const float* ffn_b3   = (const float*)d_in[29];
    float* out = (float*)d_out;

    const int UNION_U32 = (2 * ABUF) > (128 * HSTR) ? (2 * ABUF) : (128 * HSTR);
    const int LAYER_SMEM = (128 * XSTR + 128 * HSTR + UNION_U32) * 4;
    cudaFuncSetAttribute(layer_kernel, cudaFuncAttributeMaxDynamicSharedMemorySize, LAYER_SMEM);

    // 0a. weight pre-conversion (single launch)
    convert_w_kernel<<<(NWA + NWM + 255) / 256, 256>>>(in_w, skip_w, mlp_w1, mlp_w2);

    // 0b. CSR build (g_cnt arrives zeroed: static init on first call,
    //     reset inside scan_within on every call thereafter)
    count_kernel<<<(N_EDGES + 255) / 256, 256>>>(tgt);
    chunk_sum_kernel<<<NCHUNK, 256>>>();
    scan_chunks_kernel<<<1, 256>>>();
    scan_within_kernel<<<NCHUNK, 1024>>>();
    fill_kernel<<<(N_EDGES + 255) / 256, 256>>>(tgt, srcv);

    // 1. fused embedding + projection (writes fp32 x + fp16 mirror)
    proj_kernel<<<GEMM_BLKS, 256>>>(atom, hyd, deg, hyb, emb_atom, emb_h, emb_deg, emb_hyb,
                                    proj_w, proj_b);

    // 2. shell conv layers
    for (int l = 0; l < 3; l++) {
        gather_hops_kernel<<<(NSLOT * 32 + 255) / 256, 256>>>();
        layer_kernel<<<GEMM_BLKS, 512, LAYER_SMEM>>>(in_b, skip_b, mlp_b1, mlp_b2, l);
    }

    // 3. fused attention pooling + FFN readout
    pool_ffn_kernel<<<NUM_GRAPHS, 128>>>(batch, attn_w, attn_b, temp,
                                         ffn_w1, ffn_b1, ffn_w2, ffn_b2, ffn_w3, ffn_b3, out);
}

// round 16
// speedup vs baseline: 1.2069x; 1.0240x over previous
#include <cuda_runtime.h>
#include <cuda_fp16.h>

#define N_NODES   50000
#define N_EDGES   2400000
#define NUM_GRAPHS 2048
#define NSLOT     (3 * N_NODES)          // 150000 hop-slots
#define NCHUNK    ((NSLOT + 1023) / 1024) // 147
#define HID       128
#define GEMM_BLKS ((N_NODES + 127) / 128)   // 391
#define ASTR 20    // smem stride for proj streamed tiles (tf32 path)
#define XSTR 132   // smem stride (u32) for resident fp32 state
#define HSTR 68    // smem stride (u32) for resident fp16 buffers
#define CSTR 20    // smem stride (u32) for streamed fp16 chunks
#define ABUF (128 * CSTR + 256 * CSTR)   // one phase-A buffer (u32)
#define NWA  (3 * 512 * 256)             // phase-A weight elements
#define NWM  (3 * 2 * 2 * 128 * 128)     // MLP weight elements
#define CONV_BLKS ((NWA + NWM + 255) / 256)      // 2304
#define EDGE_BLKS ((N_EDGES + 255) / 256)        // 9375

// ---------------- scratch (static device memory; no allocs) ----------------
__device__ __align__(16) float  g_x[N_NODES * HID];
__device__ __align__(16) __half g_xh[N_NODES * HID];             // fp16 mirror of x
__device__ __align__(16) __half g_hops16[(size_t)N_NODES * 384]; // fp16 hop sums
__device__ __align__(16) float  g_gskip[N_NODES * HID];
// interleaved fp16 weights: [kc][n][8] tiles (kc = k/8) -> coalesced uint4 loads
__device__ __align__(16) __half g_w16A[3 * 64 * 256 * 8];        // phase A: [l][kc][n][8]
__device__ __align__(16) __half g_w16M[3 * 2 * 2 * 16 * 128 * 8];// MLP: [lm][ph][kc][n][8]
__device__ int g_cnt[NSLOT];             // zero-init; reset each launch by scan_within
__device__ int g_csum[NCHUNK];
__device__ int g_coff[NCHUNK];
__device__ int g_rowptr[NSLOT + 1];
__device__ int g_cursor[NSLOT];
__device__ int g_esrc[N_EDGES];

__device__ __forceinline__ float silu(float v) { return v / (1.f + __expf(-v)); }

__device__ __forceinline__ unsigned f2tf32(float v) {
    unsigned r;
    asm("cvt.rna.tf32.f32 %0, %1;" : "=r"(r) : "f"(v));
    return r;
}
__device__ __forceinline__ unsigned pack_half2(float a, float b) {
    __half2 h = __floats2half2_rn(a, b);
    return *(unsigned*)&h;
}
__device__ __forceinline__ void ldsm4(unsigned r[4], const unsigned* p) {
    unsigned a = (unsigned)__cvta_generic_to_shared(p);
    asm volatile("ldmatrix.sync.aligned.m8n8.x4.shared.b16 {%0,%1,%2,%3}, [%4];"
                 : "=r"(r[0]), "=r"(r[1]), "=r"(r[2]), "=r"(r[3]) : "r"(a));
}

#define MMA_TF32(cc, aa, bb) \
    asm volatile("mma.sync.aligned.m16n8k8.row.col.f32.tf32.tf32.f32 " \
                 "{%0,%1,%2,%3},{%4,%5,%6,%7},{%8,%9},{%0,%1,%2,%3};" \
                 : "+f"(cc[0]), "+f"(cc[1]), "+f"(cc[2]), "+f"(cc[3]) \
                 : "r"(aa[0]), "r"(aa[1]), "r"(aa[2]), "r"(aa[3]), \
                   "r"(bb[0]), "r"(bb[1]))

#define MMA_F16(cc, aa, b0v, b1v) \
    asm volatile("mma.sync.aligned.m16n8k16.row.col.f32.f16.f16.f32 " \
                 "{%0,%1,%2,%3},{%4,%5,%6,%7},{%8,%9},{%0,%1,%2,%3};" \
                 : "+f"(cc[0]), "+f"(cc[1]), "+f"(cc[2]), "+f"(cc[3]) \
                 : "r"(aa[0]), "r"(aa[1]), "r"(aa[2]), "r"(aa[3]), \
                   "r"(b0v), "r"(b1v))

// ====== fused: edge count (atomic histogram)  ||  weight conversion =========
__global__ void count_convert_kernel(const int* __restrict__ tgt,
                                     const float* __restrict__ in_w,
                                     const float* __restrict__ skip_w,
                                     const float* __restrict__ w1,
                                     const float* __restrict__ w2) {
    if (blockIdx.x < EDGE_BLKS) {
        int e = blockIdx.x * blockDim.x + threadIdx.x;
        if (e < N_EDGES) atomicAdd(&g_cnt[tgt[e]], 1);
    } else {
        int idx = (blockIdx.x - EDGE_BLKS) * blockDim.x + threadIdx.x;
        if (idx < NWA) {
            int l = idx / (512 * 256);
            int rem = idx % (512 * 256);
            int k = rem >> 8;
            int n = rem & 255;
            const float* src = (n < 128) ? in_w : skip_w;
            float v = src[(size_t)l * 512 * 128 + (size_t)k * 128 + (n & 127)];
            size_t dst = (((size_t)l * 64 + (k >> 3)) * 256 + n) * 8 + (k & 7);
            g_w16A[dst] = __float2half(v);
        } else if (idx < NWA + NWM) {
            int j = idx - NWA;
            int panel = j >> 14;
            int rem = j & 0x3FFF;
            int k = rem >> 7;
            int n = rem & 127;
            int phase = panel & 1;
            int lm = panel >> 1;
            const float* src = phase ? w2 : w1;
            float v = src[(size_t)lm * 16384 + (size_t)k * 128 + n];
            size_t dst = (((size_t)panel * 16 + (k >> 3)) * 128 + n) * 8 + (k & 7);
            g_w16M[dst] = __float2half(v);
        }
    }
}

// ================= CSR scan chain =================
__global__ void chunk_sum_kernel() {
    __shared__ int red[256];
    int b = blockIdx.x, t = threadIdx.x;
    int s = 0;
#pragma unroll
    for (int j = 0; j < 4; j++) {
        int i = b * 1024 + j * 256 + t;
        if (i < NSLOT) s += g_cnt[i];
    }
    red[t] = s; __syncthreads();
    for (int o = 128; o > 0; o >>= 1) {
        if (t < o) red[t] += red[t + o];
        __syncthreads();
    }
    if (t == 0) g_csum[b] = red[0];
}
__global__ void scan_chunks_kernel() {
    __shared__ int buf[2][256];
    int t = threadIdx.x;
    int v = (t < NCHUNK) ? g_csum[t] : 0;
    buf[0][t] = v;
    __syncthreads();
    int cur = 0;
#pragma unroll
    for (int off = 1; off < 256; off <<= 1) {
        int nv = buf[cur][t] + ((t >= off) ? buf[cur][t - off] : 0);
        buf[cur ^ 1][t] = nv;
        cur ^= 1;
        __syncthreads();
    }
    if (t < NCHUNK) g_coff[t] = buf[cur][t] - v;
    if (t == NCHUNK - 1) g_rowptr[NSLOT] = buf[cur][t];
}
__global__ void scan_within_kernel() {
    __shared__ int buf[2][1024];
    int b = blockIdx.x, t = threadIdx.x;
    int i = b * 1024 + t;
    int v = (i < NSLOT) ? g_cnt[i] : 0;
    buf[0][t] = v;
    __syncthreads();
    int cur = 0;
#pragma unroll
    for (int off = 1; off < 1024; off <<= 1) {
        int nv = buf[cur][t] + ((t >= off) ? buf[cur][t - off] : 0);
        buf[cur ^ 1][t] = nv;
        cur ^= 1;
        __syncthreads();
    }
    if (i < NSLOT) {
        int excl = buf[cur][t] - v;
        int rp = g_coff[b] + excl;
        g_rowptr[i] = rp;
        g_cursor[i] = rp;
        g_cnt[i] = 0;   // reset for next launch (graph replay)
    }
}

// ====== fused: proj GEMM (tensor-bound)  ||  CSR fill (atomic-bound) ========
__global__ __launch_bounds__(256) void proj_fill_kernel(
    const int* __restrict__ atom, const int* __restrict__ hyd,
    const int* __restrict__ deg,  const int* __restrict__ hyb,
    const float* __restrict__ ea, const float* __restrict__ eh,
    const float* __restrict__ ed, const float* __restrict__ ey,
    const float* __restrict__ B, const float* __restrict__ bias,
    const int* __restrict__ tgt, const int* __restrict__ srcv) {
    __shared__ unsigned Ah[128 * ASTR];
    __shared__ unsigned Bh[128 * ASTR];
    __shared__ int sidx[128][4];

    if (blockIdx.x >= GEMM_BLKS) {
        // ---------------- fill branch ----------------
        int e = (blockIdx.x - GEMM_BLKS) * blockDim.x + threadIdx.x;
        if (e < N_EDGES) {
            int t = tgt[e];
            int pos = atomicAdd(&g_cursor[t], 1);
            g_esrc[pos] = srcv[e] % N_NODES;
        }
        return;
    }

    // ---------------- proj branch (identical to R15 proj_kernel) ----------
    const int tid  = threadIdx.x;
    const int lane = tid & 31, wid = tid >> 5;
    const int wm = (wid >> 2) * 64;
    const int wn = (wid & 3) * 32;
    const int grp = lane >> 2, tg = lane & 3;
    const int row0 = blockIdx.x * 128;

    if (tid < 128) {
        int gr = row0 + tid;
        int g2 = (gr < N_NODES) ? gr : 0;
        sidx[tid][0] = atom[g2];
        sidx[tid][1] = hyd[g2];
        sidx[tid][2] = deg[g2];
        sidx[tid][3] = hyb[g2];
    }
    __syncthreads();
    const float* tabs[4] = {ea, eh, ed, ey};

    float c[4][4][4];
#pragma unroll
    for (int i = 0; i < 4; i++)
#pragma unroll
        for (int j = 0; j < 4; j++)
#pragma unroll
            for (int q = 0; q < 4; q++) c[i][j][q] = 0.f;

    const int ar  = tid >> 2;
    const int ac4 = (tid & 3) * 4;
    const int bn  = tid & 127;
    const int bk0 = (tid >> 7) * 8;

    for (int k0 = 0; k0 < 256; k0 += 16) {
        float4 av[2]; float bv[8];
        int kt = (k0 + ac4) >> 6, kw = (k0 + ac4) & 63;
#pragma unroll
        for (int it = 0; it < 2; it++) {
            int r = ar + it * 64;
            av[it] = *(const float4*)(tabs[kt] + (size_t)sidx[r][kt] * 64 + kw);
        }
#pragma unroll
        for (int kk = 0; kk < 8; kk++) bv[kk] = B[(size_t)(k0 + bk0 + kk) * 128 + bn];

        __syncthreads();
#pragma unroll
        for (int it = 0; it < 2; it++) {
            int r = ar + it * 64;
            float vv[4] = {av[it].x, av[it].y, av[it].z, av[it].w};
#pragma unroll
            for (int j = 0; j < 4; j++) Ah[r * ASTR + ac4 + j] = f2tf32(vv[j]);
        }
#pragma unroll
        for (int kk = 0; kk < 8; kk++) Bh[bn * ASTR + bk0 + kk] = f2tf32(bv[kk]);
        __syncthreads();
#pragma unroll
        for (int s = 0; s < 2; s++) {
            const int ks = s * 8;
            unsigned bh[4][2];
#pragma unroll
            for (int nf = 0; nf < 4; nf++) {
                int b0 = (wn + nf * 8 + grp) * ASTR + ks + tg;
                bh[nf][0] = Bh[b0]; bh[nf][1] = Bh[b0 + 4];
            }
#pragma unroll
            for (int mf = 0; mf < 4; mf++) {
                unsigned ah[4];
                int a0 = (wm + mf * 16 + grp) * ASTR + ks + tg;
                int a1 = a0 + 8 * ASTR;
                ah[0] = Ah[a0]; ah[1] = Ah[a1]; ah[2] = Ah[a0 + 4]; ah[3] = Ah[a1 + 4];
#pragma unroll
                for (int nf = 0; nf < 4; nf++) MMA_TF32(c[mf][nf], ah, bh[nf]);
            }
        }
    }

#pragma unroll
    for (int mf = 0; mf < 4; mf++) {
        int r0 = row0 + wm + mf * 16 + grp;
        int r1 = r0 + 8;
#pragma unroll
        for (int nf = 0; nf < 4; nf++) {
            int col = wn + nf * 8 + 2 * tg;
            float bia0 = bias[col], bia1 = bias[col + 1];
            if (r0 < N_NODES) {
                float v0 = silu(c[mf][nf][0] + bia0), v1 = silu(c[mf][nf][1] + bia1);
                g_x[(size_t)r0 * 128 + col]     = v0;
                g_x[(size_t)r0 * 128 + col + 1] = v1;
                *(unsigned*)&g_xh[(size_t)r0 * 128 + col] = pack_half2(v0, v1);
            }
            if (r1 < N_NODES) {
                float v2 = silu(c[mf][nf][2] + bia0), v3 = silu(c[mf][nf][3] + bia1);
                g_x[(size_t)r1 * 128 + col]     = v2;
                g_x[(size_t)r1 * 128 + col + 1] = v3;
                *(unsigned*)&g_xh[(size_t)r1 * 128 + col] = pack_half2(v2, v3);
            }
        }
    }
}

// ================= hop gather: fp16 rows, fp32 accum, 4-way ILP ==============
__global__ __launch_bounds__(256) void gather_hops_kernel() {
    int slot = (blockIdx.x * blockDim.x + threadIdx.x) >> 5;
    int lane = threadIdx.x & 31;
    if (slot >= NSLOT) return;
    int beg = g_rowptr[slot], end = g_rowptr[slot + 1];
    float4 a0 = make_float4(0.f,0.f,0.f,0.f), a1 = a0, a2 = a0, a3 = a0;
    const uint2* xh = (const uint2*)g_xh;
    int e = beg;
    for (; e + 3 < end; e += 4) {
        int s0 = g_esrc[e], s1 = g_esrc[e+1], s2 = g_esrc[e+2], s3 = g_esrc[e+3];
        uint2 u0 = xh[(size_t)s0 * 32 + lane];
        uint2 u1 = xh[(size_t)s1 * 32 + lane];
        uint2 u2 = xh[(size_t)s2 * 32 + lane];
        uint2 u3 = xh[(size_t)s3 * 32 + lane];
        float2 f;
        f = __half22float2(*(__half2*)&u0.x); a0.x += f.x; a0.y += f.y;
        f = __half22float2(*(__half2*)&u0.y); a0.z += f.x; a0.w += f.y;
        f = __half22float2(*(__half2*)&u1.x); a1.x += f.x; a1.y += f.y;
        f = __half22float2(*(__half2*)&u1.y); a1.z += f.x; a1.w += f.y;
        f = __half22float2(*(__half2*)&u2.x); a2.x += f.x; a2.y += f.y;
        f = __half22float2(*(__half2*)&u2.y); a2.z += f.x; a2.w += f.y;
        f = __half22float2(*(__half2*)&u3.x); a3.x += f.x; a3.y += f.y;
        f = __half22float2(*(__half2*)&u3.y); a3.z += f.x; a3.w += f.y;
    }
    for (; e < end; e++) {
        int s0 = g_esrc[e];
        uint2 u0 = xh[(size_t)s0 * 32 + lane];
        float2 f;
        f = __half22float2(*(__half2*)&u0.x); a0.x += f.x; a0.y += f.y;
        f = __half22float2(*(__half2*)&u0.y); a0.z += f.x; a0.w += f.y;
    }
    a0.x += a1.x + a2.x + a3.x;
    a0.y += a1.y + a2.y + a3.y;
    a0.z += a1.z + a2.z + a3.z;
    a0.w += a1.w + a2.w + a3.w;
    int node = slot % N_NODES, hop = slot / N_NODES;
    uint2 o;
    o.x = pack_half2(a0.x, a0.y);
    o.y = pack_half2(a0.z, a0.w);
    ((uint2*)g_hops16)[(size_t)node * 96 + hop * 32 + lane] = o;
}

// ================= mega layer kernel (fp16 MMA via ldmatrix) =================
__device__ __forceinline__ const __half* feat16_ptr(int gr, int k) {
    return (k < 128) ? (g_xh + (size_t)gr * 128 + k)
                     : (g_hops16 + (size_t)gr * 384 + (k - 128));
}

__global__ __launch_bounds__(512, 1) void layer_kernel(
    const float* __restrict__ in_b,  const float* __restrict__ skip_b,
    const float* __restrict__ mlp_b1, const float* __restrict__ mlp_b2,
    int l) {
    extern __shared__ unsigned sm[];
    float*    Xf   = (float*)sm;                 // fp32 state
    unsigned* Xh16 = sm + 128 * XSTR;            // fp16 state mirror
    unsigned* U    = Xh16 + 128 * HSTR;          // union: 2x phase-A bufs | W16
    unsigned* W16  = U;                          // MLP: weight panel (128*HSTR)

    const int tid  = threadIdx.x;
    const int lane = tid & 31, wid = tid >> 5;
    const int grp  = lane >> 2, tg = lane & 3;
    const int lrow = lane & 15;                  // ldmatrix tile row
    const int lk4  = (lane >> 4) << 2;           // ldmatrix k-half offset (u32)
    const int wm   = (wid >> 3) * 64;
    const int wni  = wid & 7;
    const int row0 = blockIdx.x * 128;

    float cA[4][4][4];
#pragma unroll
    for (int i = 0; i < 4; i++)
#pragma unroll
        for (int j = 0; j < 4; j++)
#pragma unroll
            for (int q = 0; q < 4; q++) cA[i][j][q] = 0.f;

    // ---- phase A: feats[128,512] @ W16A[l] -> N=256, fp16 MMA ----
    const int ar = tid >> 2;
    const int aq = tid & 3;
    const int bn = tid & 255;
    const int ko = (tid >> 8) * 16;
    const __half* WA = g_w16A + (size_t)l * 64 * 256 * 8;

    uint4 av, bu[2];
    {
        int gr = row0 + ar;
        av = (gr < N_NODES) ? *(const uint4*)feat16_ptr(gr, aq * 8)
                            : make_uint4(0,0,0,0);
        int c0 = ko >> 3;
        bu[0] = *(const uint4*)(WA + ((size_t)c0 * 256 + bn) * 8);
        bu[1] = *(const uint4*)(WA + ((size_t)(c0 + 1) * 256 + bn) * 8);
    }

    const int wnA = wni * 32;
    for (int k0 = 0; k0 < 512; k0 += 32) {
        unsigned* A16 = U + ((k0 >> 5) & 1) * ABUF;
        unsigned* B16 = A16 + 128 * CSTR;
        *(uint4*)&A16[ar * CSTR + aq * 4] = av;
        *(uint4*)&B16[bn * CSTR + (ko >> 1)]     = bu[0];
        *(uint4*)&B16[bn * CSTR + (ko >> 1) + 4] = bu[1];
        __syncthreads();
        if (k0 + 32 < 512) {
            int kn = k0 + 32;
            int gr = row0 + ar;
            av = (gr < N_NODES) ? *(const uint4*)feat16_ptr(gr, kn + aq * 8)
                                : make_uint4(0,0,0,0);
            int cn = (kn + ko) >> 3;
            bu[0] = *(const uint4*)(WA + ((size_t)cn * 256 + bn) * 8);
            bu[1] = *(const uint4*)(WA + ((size_t)(cn + 1) * 256 + bn) * 8);
        }
#pragma unroll
        for (int s = 0; s < 2; s++) {
            const int sb = s * 8;
            unsigned bq[2][4];
            ldsm4(bq[0], &B16[(wnA + lrow) * CSTR + sb + lk4]);
            ldsm4(bq[1], &B16[(wnA + 16 + lrow) * CSTR + sb + lk4]);
#pragma unroll
            for (int mf = 0; mf < 4; mf++) {
                unsigned ah[4];
                ldsm4(ah, &A16[(wm + mf * 16 + lrow) * CSTR + sb + lk4]);
                MMA_F16(cA[mf][0], ah, bq[0][0], bq[0][2]);
                MMA_F16(cA[mf][1], ah, bq[0][1], bq[0][3]);
                MMA_F16(cA[mf][2], ah, bq[1][0], bq[1][2]);
                MMA_F16(cA[mf][3], ah, bq[1][1], bq[1][3]);
            }
        }
    }

    // phase A epilogue: wni<4 -> h (silu) into Xf/Xh16; wni>=4 -> gskip
    {
        const float* bias = (wni < 4) ? (in_b + l * 128) : (skip_b + l * 128);
#pragma unroll
        for (int mf = 0; mf < 4; mf++) {
            int r0 = wm + mf * 16 + grp;
#pragma unroll
            for (int nf = 0; nf < 4; nf++) {
                int col = (wni & 3) * 32 + nf * 8 + 2 * tg;
                float b0 = bias[col], b1 = bias[col + 1];
                float v0 = cA[mf][nf][0] + b0, v1 = cA[mf][nf][1] + b1;
                float v2 = cA[mf][nf][2] + b0, v3 = cA[mf][nf][3] + b1;
                if (wni < 4) {
                    v0 = silu(v0); v1 = silu(v1); v2 = silu(v2); v3 = silu(v3);
                    int h2 = (col >> 1);
                    Xf[r0*XSTR + col]       = v0; Xf[r0*XSTR + col + 1]   = v1;
                    Xf[(r0+8)*XSTR + col]   = v2; Xf[(r0+8)*XSTR + col+1] = v3;
                    Xh16[r0*HSTR + h2]      = pack_half2(v0, v1);
                    Xh16[(r0+8)*HSTR + h2]  = pack_half2(v2, v3);
                } else {
                    int gr0 = row0 + r0, gr1 = gr0 + 8;
                    if (gr0 < N_NODES) { g_gskip[(size_t)gr0*128 + col] = v0; g_gskip[(size_t)gr0*128 + col+1] = v1; }
                    if (gr1 < N_NODES) { g_gskip[(size_t)gr1*128 + col] = v2; g_gskip[(size_t)gr1*128 + col+1] = v3; }
                }
            }
        }
    }
    __syncthreads();   // phase-A done before W16 overwrites U

    // ---- MLP chain: 2 blocks x 2 phases, K=128, fp16 W panel (interleaved) --
    const int wnM  = wni * 16;
    const int colW = tid & 127;
    const int kseg = (tid >> 7) * 32;

    for (int m = 0; m < 2; m++) {
        const float* B1 = mlp_b1 + (l * 2 + m) * 128;
        const float* B2 = mlp_b2 + (l * 2 + m) * 128;

        for (int phase = 0; phase < 2; phase++) {
            const __half* Wp = g_w16M + (size_t)(((l * 2 + m) * 2) + phase) * 16 * 128 * 8;

#pragma unroll
            for (int j = 0; j < 4; j++)
                *(uint4*)&W16[colW * HSTR + (kseg >> 1) + j * 4] =
                    *(const uint4*)(Wp + ((size_t)((kseg >> 3) + j) * 128 + colW) * 8);
            __syncthreads();

            float cT[4][2][4];
#pragma unroll
            for (int i = 0; i < 4; i++)
#pragma unroll
                for (int j = 0; j < 2; j++)
#pragma unroll
                    for (int q = 0; q < 4; q++) cT[i][j][q] = 0.f;

#pragma unroll
            for (int c = 0; c < 8; c++) {       // 8 x k16 steps, barrier-free
                const int cb = c * 8;
                unsigned bq[4];
                ldsm4(bq, &W16[(wnM + lrow) * HSTR + cb + lk4]);
#pragma unroll
                for (int mf = 0; mf < 4; mf++) {
                    unsigned ah[4];
                    ldsm4(ah, &Xh16[(wm + mf * 16 + lrow) * HSTR + cb + lk4]);
                    MMA_F16(cT[mf][0], ah, bq[0], bq[2]);
                    MMA_F16(cT[mf][1], ah, bq[1], bq[3]);
                }
            }

            if (phase == 0) {
                float res[4][2][4];
#pragma unroll
                for (int mf = 0; mf < 4; mf++) {
                    int r0 = wm + mf * 16 + grp;
#pragma unroll
                    for (int nf = 0; nf < 2; nf++) {
                        int col = wnM + nf * 8 + 2 * tg;
                        res[mf][nf][0] = Xf[r0*XSTR + col];
                        res[mf][nf][1] = Xf[r0*XSTR + col + 1];
                        res[mf][nf][2] = Xf[(r0+8)*XSTR + col];
                        res[mf][nf][3] = Xf[(r0+8)*XSTR + col + 1];
                        cT[mf][nf][0] = silu(cT[mf][nf][0] + B1[col]);
                        cT[mf][nf][1] = silu(cT[mf][nf][1] + B1[col + 1]);
                        cT[mf][nf][2] = silu(cT[mf][nf][2] + B1[col]);
                        cT[mf][nf][3] = silu(cT[mf][nf][3] + B1[col + 1]);
                    }
                }
                __syncthreads();   // Xh16 MMA reads done before overwrite
#pragma unroll
                for (int mf = 0; mf < 4; mf++) {
                    int r0 = wm + mf * 16 + grp;
#pragma unroll
                    for (int nf = 0; nf < 2; nf++) {
                        int col = wnM + nf * 8 + 2 * tg;
                        int h2 = col >> 1;
                        Xf[r0*XSTR+col]       = cT[mf][nf][0]; Xf[r0*XSTR+col+1]     = cT[mf][nf][1];
                        Xf[(r0+8)*XSTR+col]   = cT[mf][nf][2]; Xf[(r0+8)*XSTR+col+1] = cT[mf][nf][3];
                        Xh16[r0*HSTR + h2]     = pack_half2(cT[mf][nf][0], cT[mf][nf][1]);
                        Xh16[(r0+8)*HSTR + h2] = pack_half2(cT[mf][nf][2], cT[mf][nf][3]);
                        cA[mf][nf][0] = res[mf][nf][0]; cA[mf][nf][1] = res[mf][nf][1];
                        cA[mf][nf][2] = res[mf][nf][2]; cA[mf][nf][3] = res[mf][nf][3];
                    }
                }
                __syncthreads();
            } else {
                if (m == 0) __syncthreads();   // Xh16 reads done before overwrite
#pragma unroll
                for (int mf = 0; mf < 4; mf++) {
                    int r0 = wm + mf * 16 + grp;
#pragma unroll
                    for (int nf = 0; nf < 2; nf++) {
                        int col = wnM + nf * 8 + 2 * tg;
                        float o0 = cT[mf][nf][0] + B2[col]     + cA[mf][nf][0];
                        float o1 = cT[mf][nf][1] + B2[col + 1] + cA[mf][nf][1];
                        float o2 = cT[mf][nf][2] + B2[col]     + cA[mf][nf][2];
                        float o3 = cT[mf][nf][3] + B2[col + 1] + cA[mf][nf][3];
                        if (m == 1) {
                            int gr0 = row0 + r0, gr1 = gr0 + 8;
                            if (gr0 < N_NODES) {
                                float f0 = o0 + g_gskip[(size_t)gr0*128 + col];
                                float f1 = o1 + g_gskip[(size_t)gr0*128 + col+1];
                                g_x[(size_t)gr0*128 + col]   = f0;
                                g_x[(size_t)gr0*128 + col+1] = f1;
                                *(unsigned*)&g_xh[(size_t)gr0*128 + col] = pack_half2(f0, f1);
                            }
                            if (gr1 < N_NODES) {
                                float f2 = o2 + g_gskip[(size_t)gr1*128 + col];
                                float f3 = o3 + g_gskip[(size_t)gr1*128 + col+1];
                                g_x[(size_t)gr1*128 + col]   = f2;
                                g_x[(size_t)gr1*128 + col+1] = f3;
                                *(unsigned*)&g_xh[(size_t)gr1*128 + col] = pack_half2(f2, f3);
                            }
                        } else {
                            int h2 = col >> 1;
                            Xf[r0*XSTR+col]       = o0; Xf[r0*XSTR+col+1]     = o1;
                            Xf[(r0+8)*XSTR+col]   = o2; Xf[(r0+8)*XSTR+col+1] = o3;
                            Xh16[r0*HSTR + h2]     = pack_half2(o0, o1);
                            Xh16[(r0+8)*HSTR + h2] = pack_half2(o2, o3);
                        }
                    }
                }
                if (m == 0) __syncthreads();
            }
        }
    }
}

// ================= fused pooling + FFN: one block per graph =================
__global__ __launch_bounds__(128) void pool_ffn_kernel(
    const int* __restrict__ batch,
    const float* __restrict__ attn_w, const float* __restrict__ attn_b,
    const float* __restrict__ temp,
    const float* __restrict__ w1, const float* __restrict__ b1,
    const float* __restrict__ w2, const float* __restrict__ b2,
    const float* __restrict__ w3, const float* __restrict__ b3,
    float* __restrict__ out) {
    const int g = blockIdx.x, t = threadIdx.x;
    const int lane = t & 31, wrp = t >> 5;
    __shared__ int sbeg, send;
    __shared__ float aw[512];
    __shared__ float P[4][128];
    __shared__ float ex[128][4];
    __shared__ float m[4], s[4], rs[4];
    __shared__ float wred[4][4];
    __shared__ float p[128], h1[128], red[128];

    if (t == 0) {
        int lo = 0, hi = N_NODES;
        while (lo < hi) { int mid = (lo + hi) >> 1; if (batch[mid] < g) lo = mid + 1; else hi = mid; }
        sbeg = lo;
        hi = N_NODES;
        while (lo < hi) { int mid = (lo + hi) >> 1; if (batch[mid] < g + 1) lo = mid + 1; else hi = mid; }
        send = lo;
    }
    aw[t] = attn_w[t]; aw[128 + t] = attn_w[128 + t];
    aw[256 + t] = attn_w[256 + t]; aw[384 + t] = attn_w[384 + t];
    if (t < 4) { m[t] = -1e30f; s[t] = 0.f; }
    P[0][t] = 0.f; P[1][t] = 0.f; P[2][t] = 0.f; P[3][t] = 0.f;
    __syncthreads();
    const int beg = sbeg, end = send;
    const float invT = 1.f / temp[0];

    for (int c0 = beg; c0 < end; c0 += 128) {
        int idx = c0 + t;
        bool active = idx < end;
        float sc[4] = {-1e30f, -1e30f, -1e30f, -1e30f};
        if (active) {
            const float* xr = g_x + (size_t)idx * HID;
            float a0 = 0.f, a1 = 0.f, a2 = 0.f, a3 = 0.f;
#pragma unroll 8
            for (int k = 0; k < 128; k += 4) {
                float4 xv = *(const float4*)(xr + k);
                a0 += xv.x*aw[k]     + xv.y*aw[k+1]     + xv.z*aw[k+2]     + xv.w*aw[k+3];
                a1 += xv.x*aw[128+k] + xv.y*aw[128+k+1] + xv.z*aw[128+k+2] + xv.w*aw[128+k+3];
                a2 += xv.x*aw[256+k] + xv.y*aw[256+k+1] + xv.z*aw[256+k+2] + xv.w*aw[256+k+3];
                a3 += xv.x*aw[384+k] + xv.y*aw[384+k+1] + xv.z*aw[384+k+2] + xv.w*aw[384+k+3];
            }
            sc[0] = (a0 + attn_b[0]) * invT;
            sc[1] = (a1 + attn_b[1]) * invT;
            sc[2] = (a2 + attn_b[2]) * invT;
            sc[3] = (a3 + attn_b[3]) * invT;
        }
        float mx[4] = {sc[0], sc[1], sc[2], sc[3]};
#pragma unroll
        for (int o = 16; o; o >>= 1)
#pragma unroll
            for (int h = 0; h < 4; h++) mx[h] = fmaxf(mx[h], __shfl_xor_sync(0xffffffffu, mx[h], o));
        if (lane == 0)
#pragma unroll
            for (int h = 0; h < 4; h++) wred[wrp][h] = mx[h];
        __syncthreads();
        if (t < 4) {
            float cm = fmaxf(fmaxf(wred[0][t], wred[1][t]), fmaxf(wred[2][t], wred[3][t]));
            float nm = fmaxf(m[t], cm);
            rs[t] = __expf(m[t] - nm);
            m[t] = nm;
            s[t] *= rs[t];
        }
        __syncthreads();
        float e[4];
#pragma unroll
        for (int h = 0; h < 4; h++) {
            e[h] = active ? __expf(sc[h] - m[h]) : 0.f;
            ex[t][h] = e[h];
        }
        float sm2[4] = {e[0], e[1], e[2], e[3]};
#pragma unroll
        for (int o = 16; o; o >>= 1)
#pragma unroll
            for (int h = 0; h < 4; h++) sm2[h] += __shfl_xor_sync(0xffffffffu, sm2[h], o);
        if (lane == 0)
#pragma unroll
            for (int h = 0; h < 4; h++) wred[wrp][h] = sm2[h];
        __syncthreads();
        if (t < 4) s[t] += wred[0][t] + wred[1][t] + wred[2][t] + wred[3][t];

        int cnt = min(128, end - c0);
        float p0 = P[0][t] * rs[0], p1 = P[1][t] * rs[1];
        float p2 = P[2][t] * rs[2], p3 = P[3][t] * rs[3];
        for (int n = 0; n < cnt; n++) {
            float xv = g_x[(size_t)(c0 + n) * HID + t];
            p0 += ex[n][0] * xv;
            p1 += ex[n][1] * xv;
            p2 += ex[n][2] * xv;
            p3 += ex[n][3] * xv;
        }
        P[0][t] = p0; P[1][t] = p1; P[2][t] = p2; P[3][t] = p3;
        __syncthreads();
    }

    float pooled = 0.f;
#pragma unroll
    for (int h = 0; h < 4; h++) if (s[h] > 0.f) pooled += P[h][t] / s[h];
    p[t] = pooled * 0.25f;
    __syncthreads();

    float acc = b1[t];
#pragma unroll 8
    for (int k = 0; k < 128; k++) acc += p[k] * w1[k * 128 + t];
    h1[t] = silu(acc);
    __syncthreads();
    float acc2 = b2[t];
#pragma unroll 8
    for (int k = 0; k < 128; k++) acc2 += h1[k] * w2[k * 128 + t];
    acc2 = silu(acc2);
    red[t] = acc2 * w3[t];
    __syncthreads();
    for (int o = 64; o > 0; o >>= 1) {
        if (t < o) red[t] += red[t + o];
        __syncthreads();
    }
    if (t == 0) out[g] = red[0] + b3[0];
}

// ---------------- host launcher ---------------------------------------------
extern "C" void kernel_launch(void* const* d_in, const int* in_sizes, int n_in,
                              void* d_out, int out_size) {
    const int* atom  = (const int*)d_in[0];
    const int* hyd   = (const int*)d_in[1];
    const int* deg   = (const int*)d_in[2];
    const int* hyb   = (const int*)d_in[3];
    const int* tgt   = (const int*)d_in[4];
    const int* srcv  = (const int*)d_in[5];
    const int* batch = (const int*)d_in[6];
    const float* emb_atom = (const float*)d_in[7];
    const float* emb_h    = (const float*)d_in[8];
    const float* emb_deg  = (const float*)d_in[9];
    const float* emb_hyb  = (const float*)d_in[10];
    const float* proj_w   = (const float*)d_in[11];
    const float* proj_b   = (const float*)d_in[12];
    const float* in_w     = (const float*)d_in[13];
    const float* in_b     = (const float*)d_in[14];
    const float* mlp_w1   = (const float*)d_in[15];
    const float* mlp_b1   = (const float*)d_in[16];
    const float* mlp_w2   = (const float*)d_in[17];
    const float* mlp_b2   = (const float*)d_in[18];
    const float* skip_w   = (const float*)d_in[19];
    const float* skip_b   = (const float*)d_in[20];
    const float* attn_w   = (const float*)d_in[21];
    const float* attn_b   = (const float*)d_in[22];
    const float* temp     = (const float*)d_in[23];
    const float* ffn_w1   = (const float*)d_in[24];
    const float* ffn_b1   = (const float*)d_in[25];
    const float* ffn_w2   = (const float*)d_in[26];
    const float* ffn_b2   = (const float*)d_in[27];
    const float* ffn_w3   = (const float*)d_in[28];
    const float* ffn_b3   = (const float*)d_in[29];
    float* out = (float*)d_out;

    const int UNION_U32 = (2 * ABUF) > (128 * HSTR) ? (2 * ABUF) : (128 * HSTR);
    const int LAYER_SMEM = (128 * XSTR + 128 * HSTR + UNION_U32) * 4;
    cudaFuncSetAttribute(layer_kernel, cudaFuncAttributeMaxDynamicSharedMemorySize, LAYER_SMEM);

    // 0. fused: edge count || weight conversion (independent work, one grid)
    count_convert_kernel<<<EDGE_BLKS + CONV_BLKS, 256>>>(tgt, in_w, skip_w, mlp_w1, mlp_w2);

    // CSR scan chain
    chunk_sum_kernel<<<NCHUNK, 256>>>();
    scan_chunks_kernel<<<1, 256>>>();
    scan_within_kernel<<<NCHUNK, 1024>>>();

    // 1. fused: proj GEMM || CSR fill (independent; both feed gather)
    proj_fill_kernel<<<GEMM_BLKS + EDGE_BLKS, 256>>>(
        atom, hyd, deg, hyb, emb_atom, emb_h, emb_deg, emb_hyb,
        proj_w, proj_b, tgt, srcv);

    // 2. shell conv layers
    for (int l = 0; l < 3; l++) {
        gather_hops_kernel<<<(NSLOT * 32 + 255) / 256, 256>>>();
        layer_kernel<<<GEMM_BLKS, 512, LAYER_SMEM>>>(in_b, skip_b, mlp_b1, mlp_b2, l);
    }

    // 3. fused attention pooling + FFN readout
    pool_ffn_kernel<<<NUM_GRAPHS, 128>>>(batch, attn_w, attn_b, temp,
                                         ffn_w1, ffn_b1, ffn_w2, ffn_b2, ffn_w3, ffn_b3, out);
}